// round 11
// baseline (speedup 1.0000x reference)
#include <cuda_runtime.h>
#include <cuda_bf16.h>
#include <cstdint>

// ---------------- problem constants ----------------
#define BB 16
#define HH 56
#define WW 56
#define LL (HH*WW)      // 3136
#define DD 128
#define KK 4
#define NSEG 112
#define SEGLEN 28       // 112*28 = 3136

#define LOG2E 1.4426950408889634f
#define LN2   0.6931471805599453f

// ---------------- scratch (device globals; no allocs allowed) ----------------
__device__ float g_xz   [(size_t)BB*LL*256];     // in_proj output (xi | z), channel-last
__device__ float g_xc   [(size_t)BB*LL*DD];      // conv+silu output, channel-last
__device__ float g_proj [(size_t)BB*LL*24];      // x_dbl: per pos, [k*6 + c]
__device__ float g_ysum [(size_t)BB*LL*DD];      // pair01 y + Ds*xc
__device__ float g_ysum2[(size_t)BB*LL*DD];      // pair23 y
__device__ float g_hend [(size_t)64*NSEG*DD];
__device__ float g_aprod[(size_t)64*NSEG*DD];
__device__ float g_init [(size_t)64*NSEG*DD];

// ---------------- math helpers (MUFU) ----------------
__device__ __forceinline__ float ex2f(float x){ float y; asm("ex2.approx.ftz.f32 %0,%1;" : "=f"(y) : "f"(x)); return y; }
__device__ __forceinline__ float lg2f(float x){ float y; asm("lg2.approx.ftz.f32 %0,%1;" : "=f"(y) : "f"(x)); return y; }
__device__ __forceinline__ float rcpf(float x){ float y; asm("rcp.approx.ftz.f32 %0,%1;" : "=f"(y) : "f"(x)); return y; }
__device__ __forceinline__ float fsigmoid(float x){ return rcpf(1.f + ex2f(-x*LOG2E)); }

// softplus in log2 domain: returns u = softplus(x)*log2e
__device__ __forceinline__ float sp_u(float x){
    float tt = ex2f(fminf(x, 20.f) * LOG2E);
    return (x > 20.f) ? x * LOG2E : lg2f(1.f + tt);
}

// position for scan step: pair0 row-major, pair1 column-major
__device__ __forceinline__ int scan_pos(int pair, int s, int i){
    return (pair == 0) ? ((s>>1)*WW + (s&1)*SEGLEN + i)
                       : (((s&1)*SEGLEN + i)*WW + (s>>1));
}

// ---------------- K0: zero d_out ----------------
__global__ void k_zero(float* out){
    int i = blockIdx.x*blockDim.x + threadIdx.x;
    if (i < BB*DD) out[i] = 0.f;
}

// ---------------- tensor-core GEMM helpers ----------------
__device__ __forceinline__ void ldsm4(uint32_t* r, uint32_t addr){
    asm volatile("ldmatrix.sync.aligned.m8n8.x4.shared.b16 {%0,%1,%2,%3}, [%4];"
        : "=r"(r[0]),"=r"(r[1]),"=r"(r[2]),"=r"(r[3]) : "r"(addr));
}
__device__ __forceinline__ void mma16816(float* c, const uint32_t* a, const uint32_t* b){
    asm volatile("mma.sync.aligned.m16n8k16.row.col.f32.bf16.bf16.f32 "
        "{%0,%1,%2,%3}, {%4,%5,%6,%7}, {%8,%9}, {%0,%1,%2,%3};"
        : "+f"(c[0]),"+f"(c[1]),"+f"(c[2]),"+f"(c[3])
        : "r"(a[0]),"r"(a[1]),"r"(a[2]),"r"(a[3]), "r"(b[0]),"r"(b[1]));
}
__device__ __forceinline__ uint32_t pkbf(__nv_bfloat162 h){ return *reinterpret_cast<uint32_t*>(&h); }

// ---------------- K1: in_proj GEMM (M=50176,N=256,K=128) bf16 split-precision MMA -------
__global__ void __launch_bounds__(256) k_gemm(const float* __restrict__ X, const float* __restrict__ Wm){
    __shared__ __align__(16) __nv_bfloat16 sA[2][128][40];
    __shared__ uint32_t sB[2][64][18];
    const int t = threadIdx.x;
    const int row0 = blockIdx.x * 128;
    const int col0 = blockIdx.y * 64;
    const int wid = t >> 5, lane = t & 31;
    const int mw = wid & 3, nw = wid >> 2;
    float acc[2][4][4] = {};

    for (int kb = 0; kb < 128; kb += 32){
        #pragma unroll
        for (int j = 0; j < 4; j++){
            int fid = t + j*256;
            int r = fid >> 3, kq = (fid & 7) << 2;
            float4 v = *(const float4*)&X[(size_t)(row0+r)*128 + kb + kq];
            __nv_bfloat162 h01 = __floats2bfloat162_rn(v.x, v.y);
            __nv_bfloat162 h23 = __floats2bfloat162_rn(v.z, v.w);
            float2 f01 = __bfloat1622float2(h01);
            float2 f23 = __bfloat1622float2(h23);
            *(__nv_bfloat162*)&sA[0][r][kq]   = h01;
            *(__nv_bfloat162*)&sA[0][r][kq+2] = h23;
            *(__nv_bfloat162*)&sA[1][r][kq]   = __floats2bfloat162_rn(v.x - f01.x, v.y - f01.y);
            *(__nv_bfloat162*)&sA[1][r][kq+2] = __floats2bfloat162_rn(v.z - f23.x, v.w - f23.y);
        }
        #pragma unroll
        for (int j = 0; j < 2; j++){
            int fid = t + j*256;
            int r = fid >> 3, kq = (fid & 7) << 2;
            float4 v = *(const float4*)&Wm[(size_t)(col0+r)*128 + kb + kq];
            __nv_bfloat162 h01 = __floats2bfloat162_rn(v.x, v.y);
            __nv_bfloat162 h23 = __floats2bfloat162_rn(v.z, v.w);
            float2 f01 = __bfloat1622float2(h01);
            float2 f23 = __bfloat1622float2(h23);
            sB[0][r][(kq>>1)  ] = pkbf(h01);
            sB[0][r][(kq>>1)+1] = pkbf(h23);
            sB[1][r][(kq>>1)  ] = pkbf(__floats2bfloat162_rn(v.x - f01.x, v.y - f01.y));
            sB[1][r][(kq>>1)+1] = pkbf(__floats2bfloat162_rn(v.z - f23.x, v.w - f23.y));
        }
        __syncthreads();
        #pragma unroll
        for (int ks = 0; ks < 2; ks++){
            uint32_t ah[2][4], al[2][4];
            #pragma unroll
            for (int f = 0; f < 2; f++){
                int rr = mw*32 + f*16 + (lane & 15);
                int cc = ks*16 + (lane >> 4)*8;
                ldsm4(ah[f], (uint32_t)__cvta_generic_to_shared(&sA[0][rr][cc]));
                ldsm4(al[f], (uint32_t)__cvta_generic_to_shared(&sA[1][rr][cc]));
            }
            #pragma unroll
            for (int j = 0; j < 4; j++){
                int nr = nw*32 + j*8 + (lane >> 2);
                int kp = ks*8 + (lane & 3);
                uint32_t bh[2] = { sB[0][nr][kp], sB[0][nr][kp+4] };
                uint32_t bl[2] = { sB[1][nr][kp], sB[1][nr][kp+4] };
                #pragma unroll
                for (int f = 0; f < 2; f++){
                    mma16816(acc[f][j], ah[f], bh);
                    mma16816(acc[f][j], ah[f], bl);
                    mma16816(acc[f][j], al[f], bh);
                }
            }
        }
        __syncthreads();
    }
    #pragma unroll
    for (int f = 0; f < 2; f++){
        #pragma unroll
        for (int j = 0; j < 4; j++){
            int r = row0 + mw*32 + f*16 + (lane >> 2);
            int c = col0 + nw*32 + j*8 + (lane & 3)*2;
            *(float2*)&g_xz[(size_t)r*256 + c]     = make_float2(acc[f][j][0], acc[f][j][1]);
            *(float2*)&g_xz[(size_t)(r+8)*256 + c] = make_float2(acc[f][j][2], acc[f][j][3]);
        }
    }
}

// ---------------- K2: sliding-window depthwise conv + SiLU + fused x_dbl -----------------
__global__ void __launch_bounds__(256) k_convp(const float* __restrict__ cw, const float* __restrict__ cb,
                                               const float* __restrict__ xpw){
    __shared__ float wsh[9][128];
    __shared__ float bsh[128];
    __shared__ float wp[24][132];
    __shared__ float red[8][32][25];
    const int t = threadIdx.x;
    for (int i = t; i < 1152; i += 256) wsh[i % 9][i / 9] = cw[i];
    if (t < 128) bsh[t] = cb[t];
    for (int i = t; i < 24*128; i += 256) wp[i>>7][i&127] = xpw[i];
    __syncthreads();

    const int lane = t & 31;
    const int warpid = t >> 5;
    const int dq4 = lane*4;
    int gw = blockIdx.x*8 + warpid;
    const int ch = gw & 3; gw >>= 2;
    const int h  = gw % HH;
    const int b  = gw / HH;
    const int hm = (h > 0)    ? h-1 : 0;
    const int hp = (h < HH-1) ? h+1 : HH-1;

    float4 wreg[9];
    #pragma unroll
    for (int tap = 0; tap < 9; tap++){
        int dy = tap/3 - 1;
        int hh = h + dy;
        float4 wv = *(const float4*)&wsh[tap][dq4];
        bool ok = (hh >= 0) && (hh < HH);
        wreg[tap] = ok ? wv : make_float4(0.f,0.f,0.f,0.f);
    }
    float4 bias = *(const float4*)&bsh[dq4];

    const size_t rm = ((size_t)(b*LL + hm*WW))*256 + dq4;
    const size_t r0 = ((size_t)(b*LL + h *WW))*256 + dq4;
    const size_t rp = ((size_t)(b*LL + hp*WW))*256 + dq4;

    float4 cA[3], cB[3], cC[3];
    const float4 z4 = make_float4(0.f,0.f,0.f,0.f);
    const int w0 = ch*14;
    if (w0 > 0){
        cA[0] = *(const float4*)&g_xz[rm + (size_t)(w0-1)*256];
        cA[1] = *(const float4*)&g_xz[r0 + (size_t)(w0-1)*256];
        cA[2] = *(const float4*)&g_xz[rp + (size_t)(w0-1)*256];
    } else { cA[0]=cA[1]=cA[2]=z4; }
    cB[0] = *(const float4*)&g_xz[rm + (size_t)w0*256];
    cB[1] = *(const float4*)&g_xz[r0 + (size_t)w0*256];
    cB[2] = *(const float4*)&g_xz[rp + (size_t)w0*256];

    for (int w = w0; w < w0+14; w++){
        if (w+1 < WW){
            cC[0] = *(const float4*)&g_xz[rm + (size_t)(w+1)*256];
            cC[1] = *(const float4*)&g_xz[r0 + (size_t)(w+1)*256];
            cC[2] = *(const float4*)&g_xz[rp + (size_t)(w+1)*256];
        } else { cC[0]=cC[1]=cC[2]=z4; }

        float4 s = bias;
        #pragma unroll
        for (int r = 0; r < 3; r++){
            float4 wa = wreg[r*3+0], wb = wreg[r*3+1], wc = wreg[r*3+2];
            s.x = fmaf(cA[r].x, wa.x, s.x); s.y = fmaf(cA[r].y, wa.y, s.y);
            s.z = fmaf(cA[r].z, wa.z, s.z); s.w = fmaf(cA[r].w, wa.w, s.w);
            s.x = fmaf(cB[r].x, wb.x, s.x); s.y = fmaf(cB[r].y, wb.y, s.y);
            s.z = fmaf(cB[r].z, wb.z, s.z); s.w = fmaf(cB[r].w, wb.w, s.w);
            s.x = fmaf(cC[r].x, wc.x, s.x); s.y = fmaf(cC[r].y, wc.y, s.y);
            s.z = fmaf(cC[r].z, wc.z, s.z); s.w = fmaf(cC[r].w, wc.w, s.w);
        }
        s.x *= fsigmoid(s.x); s.y *= fsigmoid(s.y);
        s.z *= fsigmoid(s.z); s.w *= fsigmoid(s.w);
        int pos = b*LL + h*WW + w;
        *(float4*)&g_xc[(size_t)pos*128 + dq4] = s;

        #pragma unroll
        for (int c = 0; c < 24; c++){
            float4 wv = *(const float4*)&wp[c][dq4];
            red[warpid][lane][c] = s.x*wv.x + s.y*wv.y + s.z*wv.z + s.w*wv.w;
        }
        __syncwarp();
        if (lane < 24){
            float outv = 0.f;
            #pragma unroll 8
            for (int i = 0; i < 32; i++) outv += red[warpid][i][lane];
            g_proj[(size_t)pos*24 + lane] = outv;
        }
        __syncwarp();
        cA[0]=cB[0]; cA[1]=cB[1]; cA[2]=cB[2];
        cB[0]=cC[0]; cB[1]=cC[1]; cB[2]=cC[2];
    }
}

// ---------------- K3: scan pass 1 — smem-staged proj, paired dirs ----------------
__global__ void __launch_bounds__(128) k_pass1(const float* __restrict__ dtw, const float* __restrict__ dtb,
                                               const float* __restrict__ alog){
    __shared__ __align__(16) float sproj[SEGLEN][12];
    const int s = blockIdx.x, b = blockIdx.y, pair = blockIdx.z;
    const int d = threadIdx.x;
    for (int j = d; j < SEGLEN*12; j += 128){
        int i = j / 12, c = j - i*12;
        sproj[i][c] = g_proj[(size_t)(b*LL + scan_pos(pair, s, i))*24 + pair*12 + c];
    }
    const int kf = pair*2, kb_ = pair*2 + 1;
    float4 wf = *(const float4*)&dtw[(size_t)(kf*128 + d)*4];
    float4 wb = *(const float4*)&dtw[(size_t)(kb_*128 + d)*4];
    float bf = dtb[kf*128 + d], bbs = dtb[kb_*128 + d];
    float Af = -ex2f(alog[kf*128 + d] * LOG2E);
    float Ab = -ex2f(alog[kb_*128 + d] * LOG2E);
    __syncthreads();

    float hf = 0.f, Pf = 1.f;
    float hb = 0.f, Pb = 1.f;
    #pragma unroll 4
    for (int i = 0; i < SEGLEN; i++){
        int bp = b*LL + scan_pos(pair, s, i);
        float xcv = g_xc[(size_t)bp*128 + d];
        float4 f0 = *(const float4*)&sproj[i][0];
        float4 f1 = *(const float4*)&sproj[i][4];
        float4 f2 = *(const float4*)&sproj[i][8];
        float xf = fmaf(wf.x, f0.x, bf);
        xf = fmaf(wf.y, f0.y, xf);
        xf = fmaf(wf.z, f0.z, xf);
        xf = fmaf(wf.w, f0.w, xf);
        float uf = sp_u(xf);
        float daf = ex2f(Af * uf);
        float dbf = uf * LN2 * f1.x * xcv;
        hf = fmaf(daf, hf, dbf);
        Pf *= daf;
        float xb = fmaf(wb.x, f1.z, bbs);
        xb = fmaf(wb.y, f1.w, xb);
        xb = fmaf(wb.z, f2.x, xb);
        xb = fmaf(wb.w, f2.y, xb);
        float ub = sp_u(xb);
        float dab = ex2f(Ab * ub);
        float dbb = ub * LN2 * f2.z * xcv;
        hb = fmaf(dbb, Pb, hb);
        Pb *= dab;
    }
    const int gf = b*4 + kf, gb = b*4 + kb_;
    size_t if_ = ((size_t)gf*NSEG + s)*128 + d;
    size_t ib_ = ((size_t)gb*NSEG + (NSEG-1-s))*128 + d;
    g_hend[if_]  = hf;  g_aprod[if_] = Pf;
    g_hend[ib_]  = hb;  g_aprod[ib_] = Pb;
}

// ---------------- K4: combine (prefix over segments, per scan-chain) ----------------
__global__ void k_comb(){
    const int g = blockIdx.x, d = threadIdx.x;
    float carry = 0.f;
    #pragma unroll 8
    for (int s = 0; s < NSEG; s++){
        size_t idx = ((size_t)g*NSEG + s)*128 + d;
        g_init[idx] = carry;
        carry = fmaf(g_aprod[idx], carry, g_hend[idx]);
    }
}

// ---------------- K5: scan pass 2 — fwd/bwd in parallel warps, merge+store ----------
__global__ void __launch_bounds__(256) k_pass2(const float* __restrict__ dtw, const float* __restrict__ dtb,
                                               const float* __restrict__ alog, const float* __restrict__ Ds){
    __shared__ __align__(16) float sproj[SEGLEN][12];
    __shared__ float ybuf[SEGLEN][128];
    const int s = blockIdx.x, b = blockIdx.y, pair = blockIdx.z;
    const int t = threadIdx.x;
    const int d = t & 127;
    const int half = t >> 7;              // 0 = forward dir, 1 = backward dir
    for (int j = t; j < SEGLEN*12; j += 256){
        int i = j / 12, c = j - i*12;
        sproj[i][c] = g_proj[(size_t)(b*LL + scan_pos(pair, s, i))*24 + pair*12 + c];
    }
    const int k = pair*2 + half;
    float4 wv = *(const float4*)&dtw[(size_t)(k*128 + d)*4];
    float bias = dtb[k*128 + d];
    float Av = -ex2f(alog[k*128 + d] * LOG2E);
    __syncthreads();

    if (half == 1){
        // backward direction: descending traversal, write ybuf
        float hb = g_init[((size_t)(b*4 + k)*NSEG + (NSEG-1-s))*128 + d];
        #pragma unroll 4
        for (int i = SEGLEN-1; i >= 0; i--){
            int bp = b*LL + scan_pos(pair, s, i);
            float xcv = g_xc[(size_t)bp*128 + d];
            float2 g1 = *(const float2*)&sproj[i][6];   // p0b p1b
            float4 g2 = *(const float4*)&sproj[i][8];   // p2b p3b Bb Cb
            float xb = fmaf(wv.x, g1.x, bias);
            xb = fmaf(wv.y, g1.y, xb);
            xb = fmaf(wv.z, g2.x, xb);
            xb = fmaf(wv.w, g2.y, xb);
            float ub = sp_u(xb);
            float dab = ex2f(Av * ub);
            float dbb = ub * LN2 * g2.z * xcv;
            hb = fmaf(dab, hb, dbb);
            ybuf[i][d] = hb * g2.w;
        }
        __syncthreads();
    } else {
        // forward direction: ascending traversal, results in registers
        float sumDs = (pair == 0) ? (Ds[d] + Ds[128+d] + Ds[256+d] + Ds[384+d]) : 0.f;
        float yf[SEGLEN];
        float hf = g_init[((size_t)(b*4 + k)*NSEG + s)*128 + d];
        #pragma unroll
        for (int i = 0; i < SEGLEN; i++){
            int bp = b*LL + scan_pos(pair, s, i);
            float xcv = g_xc[(size_t)bp*128 + d];
            float4 f0 = *(const float4*)&sproj[i][0];   // p0f p1f p2f p3f
            float2 f1 = *(const float2*)&sproj[i][4];   // Bf Cf
            float xf = fmaf(wv.x, f0.x, bias);
            xf = fmaf(wv.y, f0.y, xf);
            xf = fmaf(wv.z, f0.z, xf);
            xf = fmaf(wv.w, f0.w, xf);
            float uf = sp_u(xf);
            float daf = ex2f(Av * uf);
            float dbf = uf * LN2 * f1.x * xcv;
            hf = fmaf(daf, hf, dbf);
            yf[i] = fmaf(hf, f1.y, (pair == 0) ? xcv*sumDs : 0.f);
        }
        __syncthreads();
        // merge with backward half's ybuf and store
        float* yout = (pair == 0) ? g_ysum : g_ysum2;
        #pragma unroll
        for (int i = 0; i < SEGLEN; i++){
            int bp = b*LL + scan_pos(pair, s, i);
            yout[(size_t)bp*128 + d] = yf[i] + ybuf[i][d];
        }
    }
}

// ---------------- K6: LayerNorm + SiLU gate + spatial mean ----------------
__global__ void __launch_bounds__(256) k_final(const float* __restrict__ nw, const float* __restrict__ nb,
                                               float* __restrict__ out){
    const int b = blockIdx.y;
    const int t = threadIdx.x;
    const int warp = t >> 5, lane = t & 31;
    const int d4 = lane*4;
    float4 w4 = *(const float4*)&nw[d4];
    float4 b4 = *(const float4*)&nb[d4];

    float4 acc = make_float4(0.f,0.f,0.f,0.f);
    #pragma unroll 2
    for (int j = 0; j < 8; j++){
        int p = blockIdx.x*64 + warp*8 + j;
        size_t base = ((size_t)(b*LL + p))*128 + d4;
        float4 v  = *(const float4*)&g_ysum[base];
        float4 v2 = *(const float4*)&g_ysum2[base];
        v.x += v2.x; v.y += v2.y; v.z += v2.z; v.w += v2.w;
        float sm = v.x+v.y+v.z+v.w;
        #pragma unroll
        for (int o = 16; o > 0; o >>= 1) sm += __shfl_xor_sync(~0u, sm, o);
        float mu = sm * (1.f/128.f);
        float4 dv = make_float4(v.x-mu, v.y-mu, v.z-mu, v.w-mu);
        float s2 = dv.x*dv.x + dv.y*dv.y + dv.z*dv.z + dv.w*dv.w;
        #pragma unroll
        for (int o = 16; o > 0; o >>= 1) s2 += __shfl_xor_sync(~0u, s2, o);
        float rstd = rsqrtf(s2 * (1.f/128.f) + 1e-5f);
        float4 z = *(const float4*)&g_xz[((size_t)(b*LL + p))*256 + 128 + d4];
        float gx = z.x*fsigmoid(z.x), gy = z.y*fsigmoid(z.y);
        float gz = z.z*fsigmoid(z.z), gw = z.w*fsigmoid(z.w);
        acc.x = fmaf(fmaf(dv.x*rstd, w4.x, b4.x), gx, acc.x);
        acc.y = fmaf(fmaf(dv.y*rstd, w4.y, b4.y), gy, acc.y);
        acc.z = fmaf(fmaf(dv.z*rstd, w4.z, b4.z), gz, acc.z);
        acc.w = fmaf(fmaf(dv.w*rstd, w4.w, b4.w), gw, acc.w);
    }
    const float sc = 1.f/(float)LL;
    atomicAdd(&out[b*128 + d4 + 0], acc.x*sc);
    atomicAdd(&out[b*128 + d4 + 1], acc.y*sc);
    atomicAdd(&out[b*128 + d4 + 2], acc.z*sc);
    atomicAdd(&out[b*128 + d4 + 3], acc.w*sc);
}

// ---------------- launch ----------------
extern "C" void kernel_launch(void* const* d_in, const int* in_sizes, int n_in,
                              void* d_out, int out_size){
    const float* x    = (const float*)d_in[0];
    const float* inw  = (const float*)d_in[1];
    const float* cw   = (const float*)d_in[2];
    const float* cb   = (const float*)d_in[3];
    const float* xpw  = (const float*)d_in[4];
    const float* dtw  = (const float*)d_in[5];
    const float* dtb  = (const float*)d_in[6];
    const float* alog = (const float*)d_in[7];
    const float* Ds   = (const float*)d_in[8];
    const float* onw  = (const float*)d_in[9];
    const float* onb  = (const float*)d_in[10];
    float* out = (float*)d_out;

    k_zero<<<(BB*DD + 255)/256, 256>>>(out);
    k_gemm<<<dim3((BB*LL)/128, 4), 256>>>(x, inw);
    k_convp<<<(BB*HH*4)/8, 256>>>(cw, cb, xpw);
    k_pass1<<<dim3(NSEG, BB, 2), 128>>>(dtw, dtb, alog);
    k_comb<<<64, 128>>>();
    k_pass2<<<dim3(NSEG, BB, 2), 256>>>(dtw, dtb, alog, Ds);
    k_final<<<dim3(LL/64, BB), 256>>>(onw, onb, out);
}

// round 12
// speedup vs baseline: 1.0795x; 1.0795x over previous
#include <cuda_runtime.h>
#include <cuda_bf16.h>
#include <cstdint>

// ---------------- problem constants ----------------
#define BB 16
#define HH 56
#define WW 56
#define LL (HH*WW)      // 3136
#define DD 128
#define KK 4
#define NSEG 112
#define SEGLEN 28       // 112*28 = 3136

#define LOG2E 1.4426950408889634f
#define LN2   0.6931471805599453f

// ---------------- scratch (device globals; no allocs allowed) ----------------
__device__ float g_xz   [(size_t)BB*LL*256];     // in_proj output (xi | z), channel-last
__device__ float g_xc   [(size_t)BB*LL*DD];      // conv+silu output, channel-last
__device__ float g_proj [(size_t)BB*LL*24];      // x_dbl: per pos, [k*6 + c]
__device__ float g_ysum [(size_t)BB*LL*DD];      // pair01 y + Ds*xc
__device__ float g_ysum2[(size_t)BB*LL*DD];      // pair23 y
__device__ float g_hend [(size_t)64*NSEG*DD];
__device__ float g_aprod[(size_t)64*NSEG*DD];
__device__ float g_init [(size_t)64*NSEG*DD];

// ---------------- math helpers (MUFU) ----------------
__device__ __forceinline__ float ex2f(float x){ float y; asm("ex2.approx.ftz.f32 %0,%1;" : "=f"(y) : "f"(x)); return y; }
__device__ __forceinline__ float lg2f(float x){ float y; asm("lg2.approx.ftz.f32 %0,%1;" : "=f"(y) : "f"(x)); return y; }
__device__ __forceinline__ float rcpf(float x){ float y; asm("rcp.approx.ftz.f32 %0,%1;" : "=f"(y) : "f"(x)); return y; }
__device__ __forceinline__ float fsigmoid(float x){ return rcpf(1.f + ex2f(-x*LOG2E)); }

// softplus in log2 domain: returns u = softplus(x)*log2e
__device__ __forceinline__ float sp_u(float x){
    float tt = ex2f(fminf(x, 20.f) * LOG2E);
    return (x > 20.f) ? x * LOG2E : lg2f(1.f + tt);
}

// position for scan step: pair0 row-major, pair1 column-major
__device__ __forceinline__ int scan_pos(int pair, int s, int i){
    return (pair == 0) ? ((s>>1)*WW + (s&1)*SEGLEN + i)
                       : (((s&1)*SEGLEN + i)*WW + (s>>1));
}

// ---------------- K0: zero d_out ----------------
__global__ void k_zero(float* out){
    int i = blockIdx.x*blockDim.x + threadIdx.x;
    if (i < BB*DD) out[i] = 0.f;
}

// ---------------- tensor-core GEMM helpers ----------------
__device__ __forceinline__ void ldsm4(uint32_t* r, uint32_t addr){
    asm volatile("ldmatrix.sync.aligned.m8n8.x4.shared.b16 {%0,%1,%2,%3}, [%4];"
        : "=r"(r[0]),"=r"(r[1]),"=r"(r[2]),"=r"(r[3]) : "r"(addr));
}
__device__ __forceinline__ void mma16816(float* c, const uint32_t* a, const uint32_t* b){
    asm volatile("mma.sync.aligned.m16n8k16.row.col.f32.bf16.bf16.f32 "
        "{%0,%1,%2,%3}, {%4,%5,%6,%7}, {%8,%9}, {%0,%1,%2,%3};"
        : "+f"(c[0]),"+f"(c[1]),"+f"(c[2]),"+f"(c[3])
        : "r"(a[0]),"r"(a[1]),"r"(a[2]),"r"(a[3]), "r"(b[0]),"r"(b[1]));
}
__device__ __forceinline__ uint32_t pkbf(__nv_bfloat162 h){ return *reinterpret_cast<uint32_t*>(&h); }

// ---------------- K1: in_proj GEMM (M=50176,N=256,K=128) bf16 split MMA, reg-prefetch ----
__global__ void __launch_bounds__(256) k_gemm(const float* __restrict__ X, const float* __restrict__ Wm){
    __shared__ __align__(16) __nv_bfloat16 sA[2][128][40];
    __shared__ uint32_t sB[2][64][18];
    const int t = threadIdx.x;
    const int row0 = blockIdx.x * 128;
    const int col0 = blockIdx.y * 64;
    const int wid = t >> 5, lane = t & 31;
    const int mw = wid & 3, nw = wid >> 2;
    float acc[2][4][4] = {};

    // per-thread load coordinates (fixed across k-blocks)
    const int ra_r  = t >> 1;                 // with j offset: (t + j*256)>>3
    float4 ra[4], rb[2];

    // prefetch k-block 0
    #pragma unroll
    for (int j = 0; j < 4; j++){
        int fid = t + j*256;
        ra[j] = *(const float4*)&X[(size_t)(row0 + (fid>>3))*128 + ((fid&7)<<2)];
    }
    #pragma unroll
    for (int j = 0; j < 2; j++){
        int fid = t + j*256;
        rb[j] = *(const float4*)&Wm[(size_t)(col0 + (fid>>3))*128 + ((fid&7)<<2)];
    }
    (void)ra_r;

    #pragma unroll
    for (int kbi = 0; kbi < 4; kbi++){
        // convert + store current regs to smem
        #pragma unroll
        for (int j = 0; j < 4; j++){
            int fid = t + j*256;
            int r = fid >> 3, kq = (fid & 7) << 2;
            float4 v = ra[j];
            __nv_bfloat162 h01 = __floats2bfloat162_rn(v.x, v.y);
            __nv_bfloat162 h23 = __floats2bfloat162_rn(v.z, v.w);
            float2 f01 = __bfloat1622float2(h01);
            float2 f23 = __bfloat1622float2(h23);
            *(__nv_bfloat162*)&sA[0][r][kq]   = h01;
            *(__nv_bfloat162*)&sA[0][r][kq+2] = h23;
            *(__nv_bfloat162*)&sA[1][r][kq]   = __floats2bfloat162_rn(v.x - f01.x, v.y - f01.y);
            *(__nv_bfloat162*)&sA[1][r][kq+2] = __floats2bfloat162_rn(v.z - f23.x, v.w - f23.y);
        }
        #pragma unroll
        for (int j = 0; j < 2; j++){
            int fid = t + j*256;
            int r = fid >> 3, kq = (fid & 7) << 2;
            float4 v = rb[j];
            __nv_bfloat162 h01 = __floats2bfloat162_rn(v.x, v.y);
            __nv_bfloat162 h23 = __floats2bfloat162_rn(v.z, v.w);
            float2 f01 = __bfloat1622float2(h01);
            float2 f23 = __bfloat1622float2(h23);
            sB[0][r][(kq>>1)  ] = pkbf(h01);
            sB[0][r][(kq>>1)+1] = pkbf(h23);
            sB[1][r][(kq>>1)  ] = pkbf(__floats2bfloat162_rn(v.x - f01.x, v.y - f01.y));
            sB[1][r][(kq>>1)+1] = pkbf(__floats2bfloat162_rn(v.z - f23.x, v.w - f23.y));
        }
        __syncthreads();

        // issue next k-block's loads (hidden under the MMA section below)
        if (kbi < 3){
            int kb = (kbi+1)*32;
            #pragma unroll
            for (int j = 0; j < 4; j++){
                int fid = t + j*256;
                ra[j] = *(const float4*)&X[(size_t)(row0 + (fid>>3))*128 + kb + ((fid&7)<<2)];
            }
            #pragma unroll
            for (int j = 0; j < 2; j++){
                int fid = t + j*256;
                rb[j] = *(const float4*)&Wm[(size_t)(col0 + (fid>>3))*128 + kb + ((fid&7)<<2)];
            }
        }

        #pragma unroll
        for (int ks = 0; ks < 2; ks++){
            uint32_t ah[2][4], al[2][4];
            #pragma unroll
            for (int f = 0; f < 2; f++){
                int rr = mw*32 + f*16 + (lane & 15);
                int cc = ks*16 + (lane >> 4)*8;
                ldsm4(ah[f], (uint32_t)__cvta_generic_to_shared(&sA[0][rr][cc]));
                ldsm4(al[f], (uint32_t)__cvta_generic_to_shared(&sA[1][rr][cc]));
            }
            #pragma unroll
            for (int j = 0; j < 4; j++){
                int nr = nw*32 + j*8 + (lane >> 2);
                int kp = ks*8 + (lane & 3);
                uint32_t bh[2] = { sB[0][nr][kp], sB[0][nr][kp+4] };
                uint32_t bl[2] = { sB[1][nr][kp], sB[1][nr][kp+4] };
                #pragma unroll
                for (int f = 0; f < 2; f++){
                    mma16816(acc[f][j], ah[f], bh);
                    mma16816(acc[f][j], ah[f], bl);
                    mma16816(acc[f][j], al[f], bh);
                }
            }
        }
        __syncthreads();
    }
    #pragma unroll
    for (int f = 0; f < 2; f++){
        #pragma unroll
        for (int j = 0; j < 4; j++){
            int r = row0 + mw*32 + f*16 + (lane >> 2);
            int c = col0 + nw*32 + j*8 + (lane & 3)*2;
            *(float2*)&g_xz[(size_t)r*256 + c]     = make_float2(acc[f][j][0], acc[f][j][1]);
            *(float2*)&g_xz[(size_t)(r+8)*256 + c] = make_float2(acc[f][j][2], acc[f][j][3]);
        }
    }
}

// ---------------- K2: sliding-window depthwise conv + SiLU + fused x_dbl -----------------
__global__ void __launch_bounds__(256) k_convp(const float* __restrict__ cw, const float* __restrict__ cb,
                                               const float* __restrict__ xpw){
    __shared__ float wsh[9][128];
    __shared__ float bsh[128];
    __shared__ float wp[24][132];
    __shared__ float red[8][32][25];
    const int t = threadIdx.x;
    for (int i = t; i < 1152; i += 256) wsh[i % 9][i / 9] = cw[i];
    if (t < 128) bsh[t] = cb[t];
    for (int i = t; i < 24*128; i += 256) wp[i>>7][i&127] = xpw[i];
    __syncthreads();

    const int lane = t & 31;
    const int warpid = t >> 5;
    const int dq4 = lane*4;
    int gw = blockIdx.x*8 + warpid;
    const int ch = gw & 3; gw >>= 2;
    const int h  = gw % HH;
    const int b  = gw / HH;
    const int hm = (h > 0)    ? h-1 : 0;
    const int hp = (h < HH-1) ? h+1 : HH-1;

    float4 wreg[9];
    #pragma unroll
    for (int tap = 0; tap < 9; tap++){
        int dy = tap/3 - 1;
        int hh = h + dy;
        float4 wv = *(const float4*)&wsh[tap][dq4];
        bool ok = (hh >= 0) && (hh < HH);
        wreg[tap] = ok ? wv : make_float4(0.f,0.f,0.f,0.f);
    }
    float4 bias = *(const float4*)&bsh[dq4];

    const size_t rm = ((size_t)(b*LL + hm*WW))*256 + dq4;
    const size_t r0 = ((size_t)(b*LL + h *WW))*256 + dq4;
    const size_t rp = ((size_t)(b*LL + hp*WW))*256 + dq4;

    float4 cA[3], cB[3], cC[3];
    const float4 z4 = make_float4(0.f,0.f,0.f,0.f);
    const int w0 = ch*14;
    if (w0 > 0){
        cA[0] = *(const float4*)&g_xz[rm + (size_t)(w0-1)*256];
        cA[1] = *(const float4*)&g_xz[r0 + (size_t)(w0-1)*256];
        cA[2] = *(const float4*)&g_xz[rp + (size_t)(w0-1)*256];
    } else { cA[0]=cA[1]=cA[2]=z4; }
    cB[0] = *(const float4*)&g_xz[rm + (size_t)w0*256];
    cB[1] = *(const float4*)&g_xz[r0 + (size_t)w0*256];
    cB[2] = *(const float4*)&g_xz[rp + (size_t)w0*256];

    for (int w = w0; w < w0+14; w++){
        if (w+1 < WW){
            cC[0] = *(const float4*)&g_xz[rm + (size_t)(w+1)*256];
            cC[1] = *(const float4*)&g_xz[r0 + (size_t)(w+1)*256];
            cC[2] = *(const float4*)&g_xz[rp + (size_t)(w+1)*256];
        } else { cC[0]=cC[1]=cC[2]=z4; }

        float4 s = bias;
        #pragma unroll
        for (int r = 0; r < 3; r++){
            float4 wa = wreg[r*3+0], wb = wreg[r*3+1], wc = wreg[r*3+2];
            s.x = fmaf(cA[r].x, wa.x, s.x); s.y = fmaf(cA[r].y, wa.y, s.y);
            s.z = fmaf(cA[r].z, wa.z, s.z); s.w = fmaf(cA[r].w, wa.w, s.w);
            s.x = fmaf(cB[r].x, wb.x, s.x); s.y = fmaf(cB[r].y, wb.y, s.y);
            s.z = fmaf(cB[r].z, wb.z, s.z); s.w = fmaf(cB[r].w, wb.w, s.w);
            s.x = fmaf(cC[r].x, wc.x, s.x); s.y = fmaf(cC[r].y, wc.y, s.y);
            s.z = fmaf(cC[r].z, wc.z, s.z); s.w = fmaf(cC[r].w, wc.w, s.w);
        }
        s.x *= fsigmoid(s.x); s.y *= fsigmoid(s.y);
        s.z *= fsigmoid(s.z); s.w *= fsigmoid(s.w);
        int pos = b*LL + h*WW + w;
        *(float4*)&g_xc[(size_t)pos*128 + dq4] = s;

        #pragma unroll
        for (int c = 0; c < 24; c++){
            float4 wv = *(const float4*)&wp[c][dq4];
            red[warpid][lane][c] = s.x*wv.x + s.y*wv.y + s.z*wv.z + s.w*wv.w;
        }
        __syncwarp();
        if (lane < 24){
            float outv = 0.f;
            #pragma unroll 8
            for (int i = 0; i < 32; i++) outv += red[warpid][i][lane];
            g_proj[(size_t)pos*24 + lane] = outv;
        }
        __syncwarp();
        cA[0]=cB[0]; cA[1]=cB[1]; cA[2]=cB[2];
        cB[0]=cC[0]; cB[1]=cC[1]; cB[2]=cC[2];
    }
}

// ---------------- K3: scan pass 1 — smem-staged proj, paired dirs ----------------
__global__ void __launch_bounds__(128) k_pass1(const float* __restrict__ dtw, const float* __restrict__ dtb,
                                               const float* __restrict__ alog){
    __shared__ __align__(16) float sproj[SEGLEN][12];
    const int s = blockIdx.x, b = blockIdx.y, pair = blockIdx.z;
    const int d = threadIdx.x;
    for (int j = d; j < SEGLEN*12; j += 128){
        int i = j / 12, c = j - i*12;
        sproj[i][c] = g_proj[(size_t)(b*LL + scan_pos(pair, s, i))*24 + pair*12 + c];
    }
    const int kf = pair*2, kb_ = pair*2 + 1;
    float4 wf = *(const float4*)&dtw[(size_t)(kf*128 + d)*4];
    float4 wb = *(const float4*)&dtw[(size_t)(kb_*128 + d)*4];
    float bf = dtb[kf*128 + d], bbs = dtb[kb_*128 + d];
    float Af = -ex2f(alog[kf*128 + d] * LOG2E);
    float Ab = -ex2f(alog[kb_*128 + d] * LOG2E);
    __syncthreads();

    float hf = 0.f, Pf = 1.f;
    float hb = 0.f, Pb = 1.f;
    #pragma unroll 4
    for (int i = 0; i < SEGLEN; i++){
        int bp = b*LL + scan_pos(pair, s, i);
        float xcv = g_xc[(size_t)bp*128 + d];
        float4 f0 = *(const float4*)&sproj[i][0];
        float4 f1 = *(const float4*)&sproj[i][4];
        float4 f2 = *(const float4*)&sproj[i][8];
        float xf = fmaf(wf.x, f0.x, bf);
        xf = fmaf(wf.y, f0.y, xf);
        xf = fmaf(wf.z, f0.z, xf);
        xf = fmaf(wf.w, f0.w, xf);
        float uf = sp_u(xf);
        float daf = ex2f(Af * uf);
        float dbf = uf * LN2 * f1.x * xcv;
        hf = fmaf(daf, hf, dbf);
        Pf *= daf;
        float xb = fmaf(wb.x, f1.z, bbs);
        xb = fmaf(wb.y, f1.w, xb);
        xb = fmaf(wb.z, f2.x, xb);
        xb = fmaf(wb.w, f2.y, xb);
        float ub = sp_u(xb);
        float dab = ex2f(Ab * ub);
        float dbb = ub * LN2 * f2.z * xcv;
        hb = fmaf(dbb, Pb, hb);
        Pb *= dab;
    }
    const int gf = b*4 + kf, gb = b*4 + kb_;
    size_t if_ = ((size_t)gf*NSEG + s)*128 + d;
    size_t ib_ = ((size_t)gb*NSEG + (NSEG-1-s))*128 + d;
    g_hend[if_]  = hf;  g_aprod[if_] = Pf;
    g_hend[ib_]  = hb;  g_aprod[ib_] = Pb;
}

// ---------------- K4: combine (prefix over segments, per scan-chain) ----------------
__global__ void k_comb(){
    const int g = blockIdx.x, d = threadIdx.x;
    float carry = 0.f;
    #pragma unroll 8
    for (int s = 0; s < NSEG; s++){
        size_t idx = ((size_t)g*NSEG + s)*128 + d;
        g_init[idx] = carry;
        carry = fmaf(g_aprod[idx], carry, g_hend[idx]);
    }
}

// ---------------- K5: scan pass 2 — smem-staged proj+xc, both pairs concurrent ----------
__global__ void __launch_bounds__(128) k_pass2(const float* __restrict__ dtw, const float* __restrict__ dtb,
                                               const float* __restrict__ alog, const float* __restrict__ Ds){
    __shared__ __align__(16) float sproj[SEGLEN][12];
    __shared__ float sxc [SEGLEN][128];
    __shared__ float ybuf[SEGLEN][128];
    const int s = blockIdx.x, b = blockIdx.y, pair = blockIdx.z;
    const int d = threadIdx.x;
    for (int j = d; j < SEGLEN*12; j += 128){
        int i = j / 12, c = j - i*12;
        sproj[i][c] = g_proj[(size_t)(b*LL + scan_pos(pair, s, i))*24 + pair*12 + c];
    }
    const int kf = pair*2, kb_ = pair*2 + 1;
    float4 wf = *(const float4*)&dtw[(size_t)(kf*128 + d)*4];
    float4 wb = *(const float4*)&dtw[(size_t)(kb_*128 + d)*4];
    float bf = dtb[kf*128 + d], bbs = dtb[kb_*128 + d];
    float Af = -ex2f(alog[kf*128 + d] * LOG2E);
    float Ab = -ex2f(alog[kb_*128 + d] * LOG2E);
    const int gf = b*4 + kf, gb = b*4 + kb_;
    __syncthreads();

    // backward direction: descending traversal; stash xc in smem
    float hb = g_init[((size_t)gb*NSEG + (NSEG-1-s))*128 + d];
    #pragma unroll 4
    for (int i = SEGLEN-1; i >= 0; i--){
        int bp = b*LL + scan_pos(pair, s, i);
        float xcv = g_xc[(size_t)bp*128 + d];
        sxc[i][d] = xcv;
        float4 f1 = *(const float4*)&sproj[i][4];   // Bf Cf p0b p1b
        float4 f2 = *(const float4*)&sproj[i][8];   // p2b p3b Bb Cb
        float xb = fmaf(wb.x, f1.z, bbs);
        xb = fmaf(wb.y, f1.w, xb);
        xb = fmaf(wb.z, f2.x, xb);
        xb = fmaf(wb.w, f2.y, xb);
        float ub = sp_u(xb);
        float dab = ex2f(Ab * ub);
        float dbb = ub * LN2 * f2.z * xcv;
        hb = fmaf(dab, hb, dbb);
        ybuf[i][d] = hb * f2.w;
    }
    // forward direction + merge (xc from smem, zero global loads)
    float sumDs = Ds[d] + Ds[128+d] + Ds[256+d] + Ds[384+d];
    float hf = g_init[((size_t)gf*NSEG + s)*128 + d];
    #pragma unroll 4
    for (int i = 0; i < SEGLEN; i++){
        int bp = b*LL + scan_pos(pair, s, i);
        float xcv = sxc[i][d];
        float4 f0 = *(const float4*)&sproj[i][0];   // p0f p1f p2f p3f
        float4 f1 = *(const float4*)&sproj[i][4];   // Bf Cf ..
        float xf = fmaf(wf.x, f0.x, bf);
        xf = fmaf(wf.y, f0.y, xf);
        xf = fmaf(wf.z, f0.z, xf);
        xf = fmaf(wf.w, f0.w, xf);
        float uf = sp_u(xf);
        float daf = ex2f(Af * uf);
        float dbf = uf * LN2 * f1.x * xcv;
        hf = fmaf(daf, hf, dbf);
        float val = fmaf(hf, f1.y, ybuf[i][d]);
        if (pair == 0){
            g_ysum[(size_t)bp*128 + d] = fmaf(xcv, sumDs, val);
        } else {
            g_ysum2[(size_t)bp*128 + d] = val;
        }
    }
}

// ---------------- K6: LayerNorm + SiLU gate + spatial mean ----------------
__global__ void __launch_bounds__(256) k_final(const float* __restrict__ nw, const float* __restrict__ nb,
                                               float* __restrict__ out){
    const int b = blockIdx.y;
    const int t = threadIdx.x;
    const int warp = t >> 5, lane = t & 31;
    const int d4 = lane*4;
    float4 w4 = *(const float4*)&nw[d4];
    float4 b4 = *(const float4*)&nb[d4];

    float4 acc = make_float4(0.f,0.f,0.f,0.f);
    #pragma unroll 2
    for (int j = 0; j < 8; j++){
        int p = blockIdx.x*64 + warp*8 + j;
        size_t base = ((size_t)(b*LL + p))*128 + d4;
        float4 v  = *(const float4*)&g_ysum[base];
        float4 v2 = *(const float4*)&g_ysum2[base];
        v.x += v2.x; v.y += v2.y; v.z += v2.z; v.w += v2.w;
        float sm = v.x+v.y+v.z+v.w;
        #pragma unroll
        for (int o = 16; o > 0; o >>= 1) sm += __shfl_xor_sync(~0u, sm, o);
        float mu = sm * (1.f/128.f);
        float4 dv = make_float4(v.x-mu, v.y-mu, v.z-mu, v.w-mu);
        float s2 = dv.x*dv.x + dv.y*dv.y + dv.z*dv.z + dv.w*dv.w;
        #pragma unroll
        for (int o = 16; o > 0; o >>= 1) s2 += __shfl_xor_sync(~0u, s2, o);
        float rstd = rsqrtf(s2 * (1.f/128.f) + 1e-5f);
        float4 z = *(const float4*)&g_xz[((size_t)(b*LL + p))*256 + 128 + d4];
        float gx = z.x*fsigmoid(z.x), gy = z.y*fsigmoid(z.y);
        float gz = z.z*fsigmoid(z.z), gw = z.w*fsigmoid(z.w);
        acc.x = fmaf(fmaf(dv.x*rstd, w4.x, b4.x), gx, acc.x);
        acc.y = fmaf(fmaf(dv.y*rstd, w4.y, b4.y), gy, acc.y);
        acc.z = fmaf(fmaf(dv.z*rstd, w4.z, b4.z), gz, acc.z);
        acc.w = fmaf(fmaf(dv.w*rstd, w4.w, b4.w), gw, acc.w);
    }
    const float sc = 1.f/(float)LL;
    atomicAdd(&out[b*128 + d4 + 0], acc.x*sc);
    atomicAdd(&out[b*128 + d4 + 1], acc.y*sc);
    atomicAdd(&out[b*128 + d4 + 2], acc.z*sc);
    atomicAdd(&out[b*128 + d4 + 3], acc.w*sc);
}

// ---------------- launch ----------------
extern "C" void kernel_launch(void* const* d_in, const int* in_sizes, int n_in,
                              void* d_out, int out_size){
    const float* x    = (const float*)d_in[0];
    const float* inw  = (const float*)d_in[1];
    const float* cw   = (const float*)d_in[2];
    const float* cb   = (const float*)d_in[3];
    const float* xpw  = (const float*)d_in[4];
    const float* dtw  = (const float*)d_in[5];
    const float* dtb  = (const float*)d_in[6];
    const float* alog = (const float*)d_in[7];
    const float* Ds   = (const float*)d_in[8];
    const float* onw  = (const float*)d_in[9];
    const float* onb  = (const float*)d_in[10];
    float* out = (float*)d_out;

    k_zero<<<(BB*DD + 255)/256, 256>>>(out);
    k_gemm<<<dim3((BB*LL)/128, 4), 256>>>(x, inw);
    k_convp<<<(BB*HH*4)/8, 256>>>(cw, cb, xpw);
    k_pass1<<<dim3(NSEG, BB, 2), 128>>>(dtw, dtb, alog);
    k_comb<<<64, 128>>>();
    k_pass2<<<dim3(NSEG, BB, 2), 128>>>(dtw, dtb, alog, Ds);
    k_final<<<dim3(LL/64, BB), 256>>>(onw, onb, out);
}

// round 13
// speedup vs baseline: 1.2021x; 1.1136x over previous
#include <cuda_runtime.h>
#include <cuda_bf16.h>
#include <cstdint>

// ---------------- problem constants ----------------
#define BB 16
#define HB 8            // batch half
#define HH 56
#define WW 56
#define LL (HH*WW)      // 3136
#define DD 128
#define KK 4
#define NSEG 112
#define SEGLEN 28       // 112*28 = 3136

#define LOG2E 1.4426950408889634f
#define LN2   0.6931471805599453f

// ---------------- scratch (device globals; no allocs allowed) ----------------
__device__ float g_xz   [(size_t)BB*LL*256];     // in_proj output (xi | z), channel-last
__device__ float g_xc   [(size_t)BB*LL*DD];      // conv+silu output, channel-last
__device__ float g_proj [(size_t)BB*LL*24];      // x_dbl: per pos, [k*6 + c]
__device__ float g_ysum [(size_t)BB*LL*DD];      // pair01 y + Ds*xc
__device__ float g_ysum2[(size_t)BB*LL*DD];      // pair23 y
__device__ float g_hend [(size_t)64*NSEG*DD];
__device__ float g_aprod[(size_t)64*NSEG*DD];
__device__ float g_init [(size_t)64*NSEG*DD];

// ---------------- math helpers (MUFU) ----------------
__device__ __forceinline__ float ex2f(float x){ float y; asm("ex2.approx.ftz.f32 %0,%1;" : "=f"(y) : "f"(x)); return y; }
__device__ __forceinline__ float lg2f(float x){ float y; asm("lg2.approx.ftz.f32 %0,%1;" : "=f"(y) : "f"(x)); return y; }
__device__ __forceinline__ float rcpf(float x){ float y; asm("rcp.approx.ftz.f32 %0,%1;" : "=f"(y) : "f"(x)); return y; }
__device__ __forceinline__ float fsigmoid(float x){ return rcpf(1.f + ex2f(-x*LOG2E)); }

// softplus in log2 domain: returns u = softplus(x)*log2e
__device__ __forceinline__ float sp_u(float x){
    float tt = ex2f(fminf(x, 20.f) * LOG2E);
    return (x > 20.f) ? x * LOG2E : lg2f(1.f + tt);
}

// position for scan step: pair0 row-major, pair1 column-major
__device__ __forceinline__ int scan_pos(int pair, int s, int i){
    return (pair == 0) ? ((s>>1)*WW + (s&1)*SEGLEN + i)
                       : (((s&1)*SEGLEN + i)*WW + (s>>1));
}

// ---------------- K0: zero d_out ----------------
__global__ void k_zero(float* out){
    int i = blockIdx.x*blockDim.x + threadIdx.x;
    if (i < BB*DD) out[i] = 0.f;
}

// ---------------- tensor-core GEMM helpers ----------------
__device__ __forceinline__ void ldsm4(uint32_t* r, uint32_t addr){
    asm volatile("ldmatrix.sync.aligned.m8n8.x4.shared.b16 {%0,%1,%2,%3}, [%4];"
        : "=r"(r[0]),"=r"(r[1]),"=r"(r[2]),"=r"(r[3]) : "r"(addr));
}
__device__ __forceinline__ void mma16816(float* c, const uint32_t* a, const uint32_t* b){
    asm volatile("mma.sync.aligned.m16n8k16.row.col.f32.bf16.bf16.f32 "
        "{%0,%1,%2,%3}, {%4,%5,%6,%7}, {%8,%9}, {%0,%1,%2,%3};"
        : "+f"(c[0]),"+f"(c[1]),"+f"(c[2]),"+f"(c[3])
        : "r"(a[0]),"r"(a[1]),"r"(a[2]),"r"(a[3]), "r"(b[0]),"r"(b[1]));
}
__device__ __forceinline__ uint32_t pkbf(__nv_bfloat162 h){ return *reinterpret_cast<uint32_t*>(&h); }

// ---------------- K1: in_proj GEMM bf16 split MMA, reg-prefetch (batch-offset) ----
__global__ void __launch_bounds__(256) k_gemm(const float* __restrict__ X, const float* __restrict__ Wm, int m0){
    __shared__ __align__(16) __nv_bfloat16 sA[2][128][40];
    __shared__ uint32_t sB[2][64][18];
    const int t = threadIdx.x;
    const int row0 = m0 + blockIdx.x * 128;
    const int col0 = blockIdx.y * 64;
    const int wid = t >> 5, lane = t & 31;
    const int mw = wid & 3, nw = wid >> 2;
    float acc[2][4][4] = {};

    float4 ra[4], rb[2];
    #pragma unroll
    for (int j = 0; j < 4; j++){
        int fid = t + j*256;
        ra[j] = *(const float4*)&X[(size_t)(row0 + (fid>>3))*128 + ((fid&7)<<2)];
    }
    #pragma unroll
    for (int j = 0; j < 2; j++){
        int fid = t + j*256;
        rb[j] = *(const float4*)&Wm[(size_t)(col0 + (fid>>3))*128 + ((fid&7)<<2)];
    }

    #pragma unroll
    for (int kbi = 0; kbi < 4; kbi++){
        #pragma unroll
        for (int j = 0; j < 4; j++){
            int fid = t + j*256;
            int r = fid >> 3, kq = (fid & 7) << 2;
            float4 v = ra[j];
            __nv_bfloat162 h01 = __floats2bfloat162_rn(v.x, v.y);
            __nv_bfloat162 h23 = __floats2bfloat162_rn(v.z, v.w);
            float2 f01 = __bfloat1622float2(h01);
            float2 f23 = __bfloat1622float2(h23);
            *(__nv_bfloat162*)&sA[0][r][kq]   = h01;
            *(__nv_bfloat162*)&sA[0][r][kq+2] = h23;
            *(__nv_bfloat162*)&sA[1][r][kq]   = __floats2bfloat162_rn(v.x - f01.x, v.y - f01.y);
            *(__nv_bfloat162*)&sA[1][r][kq+2] = __floats2bfloat162_rn(v.z - f23.x, v.w - f23.y);
        }
        #pragma unroll
        for (int j = 0; j < 2; j++){
            int fid = t + j*256;
            int r = fid >> 3, kq = (fid & 7) << 2;
            float4 v = rb[j];
            __nv_bfloat162 h01 = __floats2bfloat162_rn(v.x, v.y);
            __nv_bfloat162 h23 = __floats2bfloat162_rn(v.z, v.w);
            float2 f01 = __bfloat1622float2(h01);
            float2 f23 = __bfloat1622float2(h23);
            sB[0][r][(kq>>1)  ] = pkbf(h01);
            sB[0][r][(kq>>1)+1] = pkbf(h23);
            sB[1][r][(kq>>1)  ] = pkbf(__floats2bfloat162_rn(v.x - f01.x, v.y - f01.y));
            sB[1][r][(kq>>1)+1] = pkbf(__floats2bfloat162_rn(v.z - f23.x, v.w - f23.y));
        }
        __syncthreads();

        if (kbi < 3){
            int kb = (kbi+1)*32;
            #pragma unroll
            for (int j = 0; j < 4; j++){
                int fid = t + j*256;
                ra[j] = *(const float4*)&X[(size_t)(row0 + (fid>>3))*128 + kb + ((fid&7)<<2)];
            }
            #pragma unroll
            for (int j = 0; j < 2; j++){
                int fid = t + j*256;
                rb[j] = *(const float4*)&Wm[(size_t)(col0 + (fid>>3))*128 + kb + ((fid&7)<<2)];
            }
        }

        #pragma unroll
        for (int ks = 0; ks < 2; ks++){
            uint32_t ah[2][4], al[2][4];
            #pragma unroll
            for (int f = 0; f < 2; f++){
                int rr = mw*32 + f*16 + (lane & 15);
                int cc = ks*16 + (lane >> 4)*8;
                ldsm4(ah[f], (uint32_t)__cvta_generic_to_shared(&sA[0][rr][cc]));
                ldsm4(al[f], (uint32_t)__cvta_generic_to_shared(&sA[1][rr][cc]));
            }
            #pragma unroll
            for (int j = 0; j < 4; j++){
                int nr = nw*32 + j*8 + (lane >> 2);
                int kp = ks*8 + (lane & 3);
                uint32_t bh[2] = { sB[0][nr][kp], sB[0][nr][kp+4] };
                uint32_t bl[2] = { sB[1][nr][kp], sB[1][nr][kp+4] };
                #pragma unroll
                for (int f = 0; f < 2; f++){
                    mma16816(acc[f][j], ah[f], bh);
                    mma16816(acc[f][j], ah[f], bl);
                    mma16816(acc[f][j], al[f], bh);
                }
            }
        }
        __syncthreads();
    }
    #pragma unroll
    for (int f = 0; f < 2; f++){
        #pragma unroll
        for (int j = 0; j < 4; j++){
            int r = row0 + mw*32 + f*16 + (lane >> 2);
            int c = col0 + nw*32 + j*8 + (lane & 3)*2;
            *(float2*)&g_xz[(size_t)r*256 + c]     = make_float2(acc[f][j][0], acc[f][j][1]);
            *(float2*)&g_xz[(size_t)(r+8)*256 + c] = make_float2(acc[f][j][2], acc[f][j][3]);
        }
    }
}

// ---------------- K2: sliding-window depthwise conv + SiLU + fused x_dbl (batch-offset) --
__global__ void __launch_bounds__(256) k_convp(const float* __restrict__ cw, const float* __restrict__ cb,
                                               const float* __restrict__ xpw, int b0){
    __shared__ float wsh[9][128];
    __shared__ float bsh[128];
    __shared__ float wp[24][132];
    __shared__ float red[8][32][25];
    const int t = threadIdx.x;
    for (int i = t; i < 1152; i += 256) wsh[i % 9][i / 9] = cw[i];
    if (t < 128) bsh[t] = cb[t];
    for (int i = t; i < 24*128; i += 256) wp[i>>7][i&127] = xpw[i];
    __syncthreads();

    const int lane = t & 31;
    const int warpid = t >> 5;
    const int dq4 = lane*4;
    int gw = blockIdx.x*8 + warpid;
    const int ch = gw & 3; gw >>= 2;
    const int h  = gw % HH;
    const int b  = b0 + gw / HH;
    const int hm = (h > 0)    ? h-1 : 0;
    const int hp = (h < HH-1) ? h+1 : HH-1;

    float4 wreg[9];
    #pragma unroll
    for (int tap = 0; tap < 9; tap++){
        int dy = tap/3 - 1;
        int hh = h + dy;
        float4 wv = *(const float4*)&wsh[tap][dq4];
        bool ok = (hh >= 0) && (hh < HH);
        wreg[tap] = ok ? wv : make_float4(0.f,0.f,0.f,0.f);
    }
    float4 bias = *(const float4*)&bsh[dq4];

    const size_t rm = ((size_t)(b*LL + hm*WW))*256 + dq4;
    const size_t r0 = ((size_t)(b*LL + h *WW))*256 + dq4;
    const size_t rp = ((size_t)(b*LL + hp*WW))*256 + dq4;

    float4 cA[3], cB[3], cC[3];
    const float4 z4 = make_float4(0.f,0.f,0.f,0.f);
    const int w0 = ch*14;
    if (w0 > 0){
        cA[0] = *(const float4*)&g_xz[rm + (size_t)(w0-1)*256];
        cA[1] = *(const float4*)&g_xz[r0 + (size_t)(w0-1)*256];
        cA[2] = *(const float4*)&g_xz[rp + (size_t)(w0-1)*256];
    } else { cA[0]=cA[1]=cA[2]=z4; }
    cB[0] = *(const float4*)&g_xz[rm + (size_t)w0*256];
    cB[1] = *(const float4*)&g_xz[r0 + (size_t)w0*256];
    cB[2] = *(const float4*)&g_xz[rp + (size_t)w0*256];

    for (int w = w0; w < w0+14; w++){
        if (w+1 < WW){
            cC[0] = *(const float4*)&g_xz[rm + (size_t)(w+1)*256];
            cC[1] = *(const float4*)&g_xz[r0 + (size_t)(w+1)*256];
            cC[2] = *(const float4*)&g_xz[rp + (size_t)(w+1)*256];
        } else { cC[0]=cC[1]=cC[2]=z4; }

        float4 s = bias;
        #pragma unroll
        for (int r = 0; r < 3; r++){
            float4 wa = wreg[r*3+0], wb = wreg[r*3+1], wc = wreg[r*3+2];
            s.x = fmaf(cA[r].x, wa.x, s.x); s.y = fmaf(cA[r].y, wa.y, s.y);
            s.z = fmaf(cA[r].z, wa.z, s.z); s.w = fmaf(cA[r].w, wa.w, s.w);
            s.x = fmaf(cB[r].x, wb.x, s.x); s.y = fmaf(cB[r].y, wb.y, s.y);
            s.z = fmaf(cB[r].z, wb.z, s.z); s.w = fmaf(cB[r].w, wb.w, s.w);
            s.x = fmaf(cC[r].x, wc.x, s.x); s.y = fmaf(cC[r].y, wc.y, s.y);
            s.z = fmaf(cC[r].z, wc.z, s.z); s.w = fmaf(cC[r].w, wc.w, s.w);
        }
        s.x *= fsigmoid(s.x); s.y *= fsigmoid(s.y);
        s.z *= fsigmoid(s.z); s.w *= fsigmoid(s.w);
        int pos = b*LL + h*WW + w;
        *(float4*)&g_xc[(size_t)pos*128 + dq4] = s;

        #pragma unroll
        for (int c = 0; c < 24; c++){
            float4 wv = *(const float4*)&wp[c][dq4];
            red[warpid][lane][c] = s.x*wv.x + s.y*wv.y + s.z*wv.z + s.w*wv.w;
        }
        __syncwarp();
        if (lane < 24){
            float outv = 0.f;
            #pragma unroll 8
            for (int i = 0; i < 32; i++) outv += red[warpid][i][lane];
            g_proj[(size_t)pos*24 + lane] = outv;
        }
        __syncwarp();
        cA[0]=cB[0]; cA[1]=cB[1]; cA[2]=cB[2];
        cB[0]=cC[0]; cB[1]=cC[1]; cB[2]=cC[2];
    }
}

// ---------------- K3: scan pass 1 (batch-offset) ----------------
__global__ void __launch_bounds__(128) k_pass1(const float* __restrict__ dtw, const float* __restrict__ dtb,
                                               const float* __restrict__ alog, int b0){
    __shared__ __align__(16) float sproj[SEGLEN][12];
    const int s = blockIdx.x, b = b0 + blockIdx.y, pair = blockIdx.z;
    const int d = threadIdx.x;
    for (int j = d; j < SEGLEN*12; j += 128){
        int i = j / 12, c = j - i*12;
        sproj[i][c] = g_proj[(size_t)(b*LL + scan_pos(pair, s, i))*24 + pair*12 + c];
    }
    const int kf = pair*2, kb_ = pair*2 + 1;
    float4 wf = *(const float4*)&dtw[(size_t)(kf*128 + d)*4];
    float4 wb = *(const float4*)&dtw[(size_t)(kb_*128 + d)*4];
    float bf = dtb[kf*128 + d], bbs = dtb[kb_*128 + d];
    float Af = -ex2f(alog[kf*128 + d] * LOG2E);
    float Ab = -ex2f(alog[kb_*128 + d] * LOG2E);
    __syncthreads();

    float hf = 0.f, Pf = 1.f;
    float hb = 0.f, Pb = 1.f;
    #pragma unroll 4
    for (int i = 0; i < SEGLEN; i++){
        int bp = b*LL + scan_pos(pair, s, i);
        float xcv = g_xc[(size_t)bp*128 + d];
        float4 f0 = *(const float4*)&sproj[i][0];
        float4 f1 = *(const float4*)&sproj[i][4];
        float4 f2 = *(const float4*)&sproj[i][8];
        float xf = fmaf(wf.x, f0.x, bf);
        xf = fmaf(wf.y, f0.y, xf);
        xf = fmaf(wf.z, f0.z, xf);
        xf = fmaf(wf.w, f0.w, xf);
        float uf = sp_u(xf);
        float daf = ex2f(Af * uf);
        float dbf = uf * LN2 * f1.x * xcv;
        hf = fmaf(daf, hf, dbf);
        Pf *= daf;
        float xb = fmaf(wb.x, f1.z, bbs);
        xb = fmaf(wb.y, f1.w, xb);
        xb = fmaf(wb.z, f2.x, xb);
        xb = fmaf(wb.w, f2.y, xb);
        float ub = sp_u(xb);
        float dab = ex2f(Ab * ub);
        float dbb = ub * LN2 * f2.z * xcv;
        hb = fmaf(dbb, Pb, hb);
        Pb *= dab;
    }
    const int gf = b*4 + kf, gb = b*4 + kb_;
    size_t if_ = ((size_t)gf*NSEG + s)*128 + d;
    size_t ib_ = ((size_t)gb*NSEG + (NSEG-1-s))*128 + d;
    g_hend[if_]  = hf;  g_aprod[if_] = Pf;
    g_hend[ib_]  = hb;  g_aprod[ib_] = Pb;
}

// ---------------- K4: combine (batch-offset) ----------------
__global__ void k_comb(int b0){
    const int g = b0*4 + blockIdx.x, d = threadIdx.x;
    float carry = 0.f;
    #pragma unroll 8
    for (int s = 0; s < NSEG; s++){
        size_t idx = ((size_t)g*NSEG + s)*128 + d;
        g_init[idx] = carry;
        carry = fmaf(g_aprod[idx], carry, g_hend[idx]);
    }
}

// ---------------- K5: scan pass 2 (batch-offset) ----------------
__global__ void __launch_bounds__(128) k_pass2(const float* __restrict__ dtw, const float* __restrict__ dtb,
                                               const float* __restrict__ alog, const float* __restrict__ Ds, int b0){
    __shared__ __align__(16) float sproj[SEGLEN][12];
    __shared__ float sxc [SEGLEN][128];
    __shared__ float ybuf[SEGLEN][128];
    const int s = blockIdx.x, b = b0 + blockIdx.y, pair = blockIdx.z;
    const int d = threadIdx.x;
    for (int j = d; j < SEGLEN*12; j += 128){
        int i = j / 12, c = j - i*12;
        sproj[i][c] = g_proj[(size_t)(b*LL + scan_pos(pair, s, i))*24 + pair*12 + c];
    }
    const int kf = pair*2, kb_ = pair*2 + 1;
    float4 wf = *(const float4*)&dtw[(size_t)(kf*128 + d)*4];
    float4 wb = *(const float4*)&dtw[(size_t)(kb_*128 + d)*4];
    float bf = dtb[kf*128 + d], bbs = dtb[kb_*128 + d];
    float Af = -ex2f(alog[kf*128 + d] * LOG2E);
    float Ab = -ex2f(alog[kb_*128 + d] * LOG2E);
    const int gf = b*4 + kf, gb = b*4 + kb_;
    __syncthreads();

    float hb = g_init[((size_t)gb*NSEG + (NSEG-1-s))*128 + d];
    #pragma unroll 4
    for (int i = SEGLEN-1; i >= 0; i--){
        int bp = b*LL + scan_pos(pair, s, i);
        float xcv = g_xc[(size_t)bp*128 + d];
        sxc[i][d] = xcv;
        float4 f1 = *(const float4*)&sproj[i][4];
        float4 f2 = *(const float4*)&sproj[i][8];
        float xb = fmaf(wb.x, f1.z, bbs);
        xb = fmaf(wb.y, f1.w, xb);
        xb = fmaf(wb.z, f2.x, xb);
        xb = fmaf(wb.w, f2.y, xb);
        float ub = sp_u(xb);
        float dab = ex2f(Ab * ub);
        float dbb = ub * LN2 * f2.z * xcv;
        hb = fmaf(dab, hb, dbb);
        ybuf[i][d] = hb * f2.w;
    }
    float sumDs = Ds[d] + Ds[128+d] + Ds[256+d] + Ds[384+d];
    float hf = g_init[((size_t)gf*NSEG + s)*128 + d];
    #pragma unroll 4
    for (int i = 0; i < SEGLEN; i++){
        int bp = b*LL + scan_pos(pair, s, i);
        float xcv = sxc[i][d];
        float4 f0 = *(const float4*)&sproj[i][0];
        float4 f1 = *(const float4*)&sproj[i][4];
        float xf = fmaf(wf.x, f0.x, bf);
        xf = fmaf(wf.y, f0.y, xf);
        xf = fmaf(wf.z, f0.z, xf);
        xf = fmaf(wf.w, f0.w, xf);
        float uf = sp_u(xf);
        float daf = ex2f(Af * uf);
        float dbf = uf * LN2 * f1.x * xcv;
        hf = fmaf(daf, hf, dbf);
        float val = fmaf(hf, f1.y, ybuf[i][d]);
        if (pair == 0){
            g_ysum[(size_t)bp*128 + d] = fmaf(xcv, sumDs, val);
        } else {
            g_ysum2[(size_t)bp*128 + d] = val;
        }
    }
}

// ---------------- K6: LayerNorm + SiLU gate + spatial mean (batch-offset) ----------------
__global__ void __launch_bounds__(256) k_final(const float* __restrict__ nw, const float* __restrict__ nb,
                                               float* __restrict__ out, int b0){
    const int b = b0 + blockIdx.y;
    const int t = threadIdx.x;
    const int warp = t >> 5, lane = t & 31;
    const int d4 = lane*4;
    float4 w4 = *(const float4*)&nw[d4];
    float4 b4 = *(const float4*)&nb[d4];

    float4 acc = make_float4(0.f,0.f,0.f,0.f);
    #pragma unroll 2
    for (int j = 0; j < 8; j++){
        int p = blockIdx.x*64 + warp*8 + j;
        size_t base = ((size_t)(b*LL + p))*128 + d4;
        float4 v  = *(const float4*)&g_ysum[base];
        float4 v2 = *(const float4*)&g_ysum2[base];
        v.x += v2.x; v.y += v2.y; v.z += v2.z; v.w += v2.w;
        float sm = v.x+v.y+v.z+v.w;
        #pragma unroll
        for (int o = 16; o > 0; o >>= 1) sm += __shfl_xor_sync(~0u, sm, o);
        float mu = sm * (1.f/128.f);
        float4 dv = make_float4(v.x-mu, v.y-mu, v.z-mu, v.w-mu);
        float s2 = dv.x*dv.x + dv.y*dv.y + dv.z*dv.z + dv.w*dv.w;
        #pragma unroll
        for (int o = 16; o > 0; o >>= 1) s2 += __shfl_xor_sync(~0u, s2, o);
        float rstd = rsqrtf(s2 * (1.f/128.f) + 1e-5f);
        float4 z = *(const float4*)&g_xz[((size_t)(b*LL + p))*256 + 128 + d4];
        float gx = z.x*fsigmoid(z.x), gy = z.y*fsigmoid(z.y);
        float gz = z.z*fsigmoid(z.z), gw = z.w*fsigmoid(z.w);
        acc.x = fmaf(fmaf(dv.x*rstd, w4.x, b4.x), gx, acc.x);
        acc.y = fmaf(fmaf(dv.y*rstd, w4.y, b4.y), gy, acc.y);
        acc.z = fmaf(fmaf(dv.z*rstd, w4.z, b4.z), gz, acc.z);
        acc.w = fmaf(fmaf(dv.w*rstd, w4.w, b4.w), gw, acc.w);
    }
    const float sc = 1.f/(float)LL;
    atomicAdd(&out[b*128 + d4 + 0], acc.x*sc);
    atomicAdd(&out[b*128 + d4 + 1], acc.y*sc);
    atomicAdd(&out[b*128 + d4 + 2], acc.z*sc);
    atomicAdd(&out[b*128 + d4 + 3], acc.w*sc);
}

// ---------------- launch: two batch-half chains on forked streams ----------------
extern "C" void kernel_launch(void* const* d_in, const int* in_sizes, int n_in,
                              void* d_out, int out_size){
    const float* x    = (const float*)d_in[0];
    const float* inw  = (const float*)d_in[1];
    const float* cw   = (const float*)d_in[2];
    const float* cb   = (const float*)d_in[3];
    const float* xpw  = (const float*)d_in[4];
    const float* dtw  = (const float*)d_in[5];
    const float* dtb  = (const float*)d_in[6];
    const float* alog = (const float*)d_in[7];
    const float* Ds   = (const float*)d_in[8];
    const float* onw  = (const float*)d_in[9];
    const float* onb  = (const float*)d_in[10];
    float* out = (float*)d_out;

    static cudaStream_t sA = nullptr, sB = nullptr;
    static cudaEvent_t  e0 = nullptr, eA = nullptr, eB = nullptr;
    if (!sA){
        cudaStreamCreateWithFlags(&sA, cudaStreamNonBlocking);
        cudaStreamCreateWithFlags(&sB, cudaStreamNonBlocking);
        cudaEventCreateWithFlags(&e0, cudaEventDisableTiming);
        cudaEventCreateWithFlags(&eA, cudaEventDisableTiming);
        cudaEventCreateWithFlags(&eB, cudaEventDisableTiming);
    }

    k_zero<<<(BB*DD + 255)/256, 256>>>(out);
    cudaEventRecord(e0, 0);
    cudaStreamWaitEvent(sA, e0, 0);
    cudaStreamWaitEvent(sB, e0, 0);

    cudaStream_t ss[2] = { sA, sB };
    #pragma unroll
    for (int hhalf = 0; hhalf < 2; hhalf++){
        cudaStream_t st = ss[hhalf];
        const int b0 = hhalf * HB;
        k_gemm <<<dim3((HB*LL)/128, 4), 256, 0, st>>>(x, inw, b0*LL);
        k_convp<<<(HB*HH*4)/8, 256, 0, st>>>(cw, cb, xpw, b0);
        k_pass1<<<dim3(NSEG, HB, 2), 128, 0, st>>>(dtw, dtb, alog, b0);
        k_comb <<<HB*4, 128, 0, st>>>(b0);
        k_pass2<<<dim3(NSEG, HB, 2), 128, 0, st>>>(dtw, dtb, alog, Ds, b0);
        k_final<<<dim3(LL/64, HB), 256, 0, st>>>(onw, onb, out, b0);
    }
    cudaEventRecord(eA, sA);
    cudaEventRecord(eB, sB);
    cudaStreamWaitEvent(0, eA, 0);
    cudaStreamWaitEvent(0, eB, 0);
}

// round 15
// speedup vs baseline: 1.2060x; 1.0032x over previous
#include <cuda_runtime.h>
#include <cuda_bf16.h>
#include <cstdint>

// ---------------- problem constants ----------------
#define BB 16
#define HB 8            // batch half
#define HH 56
#define WW 56
#define LL (HH*WW)      // 3136
#define DD 128
#define KK 4
#define NSEG 112
#define SEGLEN 28       // 112*28 = 3136

#define LOG2E 1.4426950408889634f
#define LN2   0.6931471805599453f

// ---------------- scratch (device globals; no allocs allowed) ----------------
__device__ float g_xz   [(size_t)BB*LL*256];           // in_proj output (xi | z)
__device__ float g_xc   [(size_t)BB*LL*DD];            // conv+silu output
__device__ float g_proj [(size_t)BB*LL*24];            // x_dbl per pos
__device__ __nv_bfloat16 g_ysum [(size_t)BB*LL*DD];    // pair01 y + Ds*xc (bf16)
__device__ __nv_bfloat16 g_ysum2[(size_t)BB*LL*DD];    // pair23 y (bf16)
__device__ float g_hend [(size_t)64*NSEG*DD];
__device__ float g_aprod[(size_t)64*NSEG*DD];
__device__ float g_init [(size_t)64*NSEG*DD];

// ---------------- math helpers (MUFU) ----------------
__device__ __forceinline__ float ex2f(float x){ float y; asm("ex2.approx.ftz.f32 %0,%1;" : "=f"(y) : "f"(x)); return y; }
__device__ __forceinline__ float lg2f(float x){ float y; asm("lg2.approx.ftz.f32 %0,%1;" : "=f"(y) : "f"(x)); return y; }
__device__ __forceinline__ float rcpf(float x){ float y; asm("rcp.approx.ftz.f32 %0,%1;" : "=f"(y) : "f"(x)); return y; }
__device__ __forceinline__ float fsigmoid(float x){ return rcpf(1.f + ex2f(-x*LOG2E)); }

// softplus in log2 domain: returns u = softplus(x)*log2e
__device__ __forceinline__ float sp_u(float x){
    float tt = ex2f(fminf(x, 20.f) * LOG2E);
    return (x > 20.f) ? x * LOG2E : lg2f(1.f + tt);
}

// position for scan step: pair0 row-major, pair1 column-major
__device__ __forceinline__ int scan_pos(int pair, int s, int i){
    return (pair == 0) ? ((s>>1)*WW + (s&1)*SEGLEN + i)
                       : (((s&1)*SEGLEN + i)*WW + (s>>1));
}

// ---------------- K0: zero d_out ----------------
__global__ void k_zero(float* out){
    int i = blockIdx.x*blockDim.x + threadIdx.x;
    if (i < BB*DD) out[i] = 0.f;
}

// ---------------- tensor-core GEMM helpers ----------------
__device__ __forceinline__ void ldsm4(uint32_t* r, uint32_t addr){
    asm volatile("ldmatrix.sync.aligned.m8n8.x4.shared.b16 {%0,%1,%2,%3}, [%4];"
        : "=r"(r[0]),"=r"(r[1]),"=r"(r[2]),"=r"(r[3]) : "r"(addr));
}
__device__ __forceinline__ void mma16816(float* c, const uint32_t* a, const uint32_t* b){
    asm volatile("mma.sync.aligned.m16n8k16.row.col.f32.bf16.bf16.f32 "
        "{%0,%1,%2,%3}, {%4,%5,%6,%7}, {%8,%9}, {%0,%1,%2,%3};"
        : "+f"(c[0]),"+f"(c[1]),"+f"(c[2]),"+f"(c[3])
        : "r"(a[0]),"r"(a[1]),"r"(a[2]),"r"(a[3]), "r"(b[0]),"r"(b[1]));
}
__device__ __forceinline__ uint32_t pkbf(__nv_bfloat162 h){ return *reinterpret_cast<uint32_t*>(&h); }

// ---------------- K1: in_proj GEMM bf16 split MMA, reg-prefetch (batch-offset) ----
__global__ void __launch_bounds__(256) k_gemm(const float* __restrict__ X, const float* __restrict__ Wm, int m0){
    __shared__ __align__(16) __nv_bfloat16 sA[2][128][40];
    __shared__ uint32_t sB[2][64][18];
    const int t = threadIdx.x;
    const int row0 = m0 + blockIdx.x * 128;
    const int col0 = blockIdx.y * 64;
    const int wid = t >> 5, lane = t & 31;
    const int mw = wid & 3, nw = wid >> 2;
    float acc[2][4][4] = {};

    float4 ra[4], rb[2];
    #pragma unroll
    for (int j = 0; j < 4; j++){
        int fid = t + j*256;
        ra[j] = *(const float4*)&X[(size_t)(row0 + (fid>>3))*128 + ((fid&7)<<2)];
    }
    #pragma unroll
    for (int j = 0; j < 2; j++){
        int fid = t + j*256;
        rb[j] = *(const float4*)&Wm[(size_t)(col0 + (fid>>3))*128 + ((fid&7)<<2)];
    }

    #pragma unroll
    for (int kbi = 0; kbi < 4; kbi++){
        #pragma unroll
        for (int j = 0; j < 4; j++){
            int fid = t + j*256;
            int r = fid >> 3, kq = (fid & 7) << 2;
            float4 v = ra[j];
            __nv_bfloat162 h01 = __floats2bfloat162_rn(v.x, v.y);
            __nv_bfloat162 h23 = __floats2bfloat162_rn(v.z, v.w);
            float2 f01 = __bfloat1622float2(h01);
            float2 f23 = __bfloat1622float2(h23);
            *(__nv_bfloat162*)&sA[0][r][kq]   = h01;
            *(__nv_bfloat162*)&sA[0][r][kq+2] = h23;
            *(__nv_bfloat162*)&sA[1][r][kq]   = __floats2bfloat162_rn(v.x - f01.x, v.y - f01.y);
            *(__nv_bfloat162*)&sA[1][r][kq+2] = __floats2bfloat162_rn(v.z - f23.x, v.w - f23.y);
        }
        #pragma unroll
        for (int j = 0; j < 2; j++){
            int fid = t + j*256;
            int r = fid >> 3, kq = (fid & 7) << 2;
            float4 v = rb[j];
            __nv_bfloat162 h01 = __floats2bfloat162_rn(v.x, v.y);
            __nv_bfloat162 h23 = __floats2bfloat162_rn(v.z, v.w);
            float2 f01 = __bfloat1622float2(h01);
            float2 f23 = __bfloat1622float2(h23);
            sB[0][r][(kq>>1)  ] = pkbf(h01);
            sB[0][r][(kq>>1)+1] = pkbf(h23);
            sB[1][r][(kq>>1)  ] = pkbf(__floats2bfloat162_rn(v.x - f01.x, v.y - f01.y));
            sB[1][r][(kq>>1)+1] = pkbf(__floats2bfloat162_rn(v.z - f23.x, v.w - f23.y));
        }
        __syncthreads();

        if (kbi < 3){
            int kb = (kbi+1)*32;
            #pragma unroll
            for (int j = 0; j < 4; j++){
                int fid = t + j*256;
                ra[j] = *(const float4*)&X[(size_t)(row0 + (fid>>3))*128 + kb + ((fid&7)<<2)];
            }
            #pragma unroll
            for (int j = 0; j < 2; j++){
                int fid = t + j*256;
                rb[j] = *(const float4*)&Wm[(size_t)(col0 + (fid>>3))*128 + kb + ((fid&7)<<2)];
            }
        }

        #pragma unroll
        for (int ks = 0; ks < 2; ks++){
            uint32_t ah[2][4], al[2][4];
            #pragma unroll
            for (int f = 0; f < 2; f++){
                int rr = mw*32 + f*16 + (lane & 15);
                int cc = ks*16 + (lane >> 4)*8;
                ldsm4(ah[f], (uint32_t)__cvta_generic_to_shared(&sA[0][rr][cc]));
                ldsm4(al[f], (uint32_t)__cvta_generic_to_shared(&sA[1][rr][cc]));
            }
            #pragma unroll
            for (int j = 0; j < 4; j++){
                int nr = nw*32 + j*8 + (lane >> 2);
                int kp = ks*8 + (lane & 3);
                uint32_t bh[2] = { sB[0][nr][kp], sB[0][nr][kp+4] };
                uint32_t bl[2] = { sB[1][nr][kp], sB[1][nr][kp+4] };
                #pragma unroll
                for (int f = 0; f < 2; f++){
                    mma16816(acc[f][j], ah[f], bh);
                    mma16816(acc[f][j], ah[f], bl);
                    mma16816(acc[f][j], al[f], bh);
                }
            }
        }
        __syncthreads();
    }
    #pragma unroll
    for (int f = 0; f < 2; f++){
        #pragma unroll
        for (int j = 0; j < 4; j++){
            int r = row0 + mw*32 + f*16 + (lane >> 2);
            int c = col0 + nw*32 + j*8 + (lane & 3)*2;
            *(float2*)&g_xz[(size_t)r*256 + c]     = make_float2(acc[f][j][0], acc[f][j][1]);
            *(float2*)&g_xz[(size_t)(r+8)*256 + c] = make_float2(acc[f][j][2], acc[f][j][3]);
        }
    }
}

// ---------------- K2: sliding-window depthwise conv + SiLU + fused x_dbl (batch-offset) --
__global__ void __launch_bounds__(256) k_convp(const float* __restrict__ cw, const float* __restrict__ cb,
                                               const float* __restrict__ xpw, int b0){
    __shared__ float wsh[9][128];
    __shared__ float bsh[128];
    __shared__ float wp[24][132];
    __shared__ float red[8][32][25];
    const int t = threadIdx.x;
    for (int i = t; i < 1152; i += 256) wsh[i % 9][i / 9] = cw[i];
    if (t < 128) bsh[t] = cb[t];
    for (int i = t; i < 24*128; i += 256) wp[i>>7][i&127] = xpw[i];
    __syncthreads();

    const int lane = t & 31;
    const int warpid = t >> 5;
    const int dq4 = lane*4;
    int gw = blockIdx.x*8 + warpid;
    const int ch = gw & 3; gw >>= 2;
    const int h  = gw % HH;
    const int b  = b0 + gw / HH;
    const int hm = (h > 0)    ? h-1 : 0;
    const int hp = (h < HH-1) ? h+1 : HH-1;

    float4 wreg[9];
    #pragma unroll
    for (int tap = 0; tap < 9; tap++){
        int dy = tap/3 - 1;
        int hh = h + dy;
        float4 wv = *(const float4*)&wsh[tap][dq4];
        bool ok = (hh >= 0) && (hh < HH);
        wreg[tap] = ok ? wv : make_float4(0.f,0.f,0.f,0.f);
    }
    float4 bias = *(const float4*)&bsh[dq4];

    const size_t rm = ((size_t)(b*LL + hm*WW))*256 + dq4;
    const size_t r0 = ((size_t)(b*LL + h *WW))*256 + dq4;
    const size_t rp = ((size_t)(b*LL + hp*WW))*256 + dq4;

    float4 cA[3], cB[3], cC[3];
    const float4 z4 = make_float4(0.f,0.f,0.f,0.f);
    const int w0 = ch*14;
    if (w0 > 0){
        cA[0] = *(const float4*)&g_xz[rm + (size_t)(w0-1)*256];
        cA[1] = *(const float4*)&g_xz[r0 + (size_t)(w0-1)*256];
        cA[2] = *(const float4*)&g_xz[rp + (size_t)(w0-1)*256];
    } else { cA[0]=cA[1]=cA[2]=z4; }
    cB[0] = *(const float4*)&g_xz[rm + (size_t)w0*256];
    cB[1] = *(const float4*)&g_xz[r0 + (size_t)w0*256];
    cB[2] = *(const float4*)&g_xz[rp + (size_t)w0*256];

    for (int w = w0; w < w0+14; w++){
        if (w+1 < WW){
            cC[0] = *(const float4*)&g_xz[rm + (size_t)(w+1)*256];
            cC[1] = *(const float4*)&g_xz[r0 + (size_t)(w+1)*256];
            cC[2] = *(const float4*)&g_xz[rp + (size_t)(w+1)*256];
        } else { cC[0]=cC[1]=cC[2]=z4; }

        float4 s = bias;
        #pragma unroll
        for (int r = 0; r < 3; r++){
            float4 wa = wreg[r*3+0], wb = wreg[r*3+1], wc = wreg[r*3+2];
            s.x = fmaf(cA[r].x, wa.x, s.x); s.y = fmaf(cA[r].y, wa.y, s.y);
            s.z = fmaf(cA[r].z, wa.z, s.z); s.w = fmaf(cA[r].w, wa.w, s.w);
            s.x = fmaf(cB[r].x, wb.x, s.x); s.y = fmaf(cB[r].y, wb.y, s.y);
            s.z = fmaf(cB[r].z, wb.z, s.z); s.w = fmaf(cB[r].w, wb.w, s.w);
            s.x = fmaf(cC[r].x, wc.x, s.x); s.y = fmaf(cC[r].y, wc.y, s.y);
            s.z = fmaf(cC[r].z, wc.z, s.z); s.w = fmaf(cC[r].w, wc.w, s.w);
        }
        s.x *= fsigmoid(s.x); s.y *= fsigmoid(s.y);
        s.z *= fsigmoid(s.z); s.w *= fsigmoid(s.w);
        int pos = b*LL + h*WW + w;
        *(float4*)&g_xc[(size_t)pos*128 + dq4] = s;

        #pragma unroll
        for (int c = 0; c < 24; c++){
            float4 wv = *(const float4*)&wp[c][dq4];
            red[warpid][lane][c] = s.x*wv.x + s.y*wv.y + s.z*wv.z + s.w*wv.w;
        }
        __syncwarp();
        if (lane < 24){
            float outv = 0.f;
            #pragma unroll 8
            for (int i = 0; i < 32; i++) outv += red[warpid][i][lane];
            g_proj[(size_t)pos*24 + lane] = outv;
        }
        __syncwarp();
        cA[0]=cB[0]; cA[1]=cB[1]; cA[2]=cB[2];
        cB[0]=cC[0]; cB[1]=cC[1]; cB[2]=cC[2];
    }
}

// ---------------- K3: scan pass 1 (batch-offset) ----------------
__global__ void __launch_bounds__(128) k_pass1(const float* __restrict__ dtw, const float* __restrict__ dtb,
                                               const float* __restrict__ alog, int b0){
    __shared__ __align__(16) float sproj[SEGLEN][12];
    const int s = blockIdx.x, b = b0 + blockIdx.y, pair = blockIdx.z;
    const int d = threadIdx.x;
    for (int j = d; j < SEGLEN*12; j += 128){
        int i = j / 12, c = j - i*12;
        sproj[i][c] = g_proj[(size_t)(b*LL + scan_pos(pair, s, i))*24 + pair*12 + c];
    }
    const int kf = pair*2, kb_ = pair*2 + 1;
    float4 wf = *(const float4*)&dtw[(size_t)(kf*128 + d)*4];
    float4 wb = *(const float4*)&dtw[(size_t)(kb_*128 + d)*4];
    float bf = dtb[kf*128 + d], bbs = dtb[kb_*128 + d];
    float Af = -ex2f(alog[kf*128 + d] * LOG2E);
    float Ab = -ex2f(alog[kb_*128 + d] * LOG2E);
    __syncthreads();

    float hf = 0.f, Pf = 1.f;
    float hb = 0.f, Pb = 1.f;
    #pragma unroll 4
    for (int i = 0; i < SEGLEN; i++){
        int bp = b*LL + scan_pos(pair, s, i);
        float xcv = g_xc[(size_t)bp*128 + d];
        float4 f0 = *(const float4*)&sproj[i][0];
        float4 f1 = *(const float4*)&sproj[i][4];
        float4 f2 = *(const float4*)&sproj[i][8];
        float xf = fmaf(wf.x, f0.x, bf);
        xf = fmaf(wf.y, f0.y, xf);
        xf = fmaf(wf.z, f0.z, xf);
        xf = fmaf(wf.w, f0.w, xf);
        float uf = sp_u(xf);
        float daf = ex2f(Af * uf);
        float dbf = uf * LN2 * f1.x * xcv;
        hf = fmaf(daf, hf, dbf);
        Pf *= daf;
        float xb = fmaf(wb.x, f1.z, bbs);
        xb = fmaf(wb.y, f1.w, xb);
        xb = fmaf(wb.z, f2.x, xb);
        xb = fmaf(wb.w, f2.y, xb);
        float ub = sp_u(xb);
        float dab = ex2f(Ab * ub);
        float dbb = ub * LN2 * f2.z * xcv;
        hb = fmaf(dbb, Pb, hb);
        Pb *= dab;
    }
    const int gf = b*4 + kf, gb = b*4 + kb_;
    size_t if_ = ((size_t)gf*NSEG + s)*128 + d;
    size_t ib_ = ((size_t)gb*NSEG + (NSEG-1-s))*128 + d;
    g_hend[if_]  = hf;  g_aprod[if_] = Pf;
    g_hend[ib_]  = hb;  g_aprod[ib_] = Pb;
}

// ---------------- K4: combine (batch-offset) ----------------
__global__ void k_comb(int b0){
    const int g = b0*4 + blockIdx.x, d = threadIdx.x;
    float carry = 0.f;
    #pragma unroll 8
    for (int s = 0; s < NSEG; s++){
        size_t idx = ((size_t)g*NSEG + s)*128 + d;
        g_init[idx] = carry;
        carry = fmaf(g_aprod[idx], carry, g_hend[idx]);
    }
}

// ---------------- K5: scan pass 2 (batch-offset, bf16 y output) ----------------
__global__ void __launch_bounds__(128) k_pass2(const float* __restrict__ dtw, const float* __restrict__ dtb,
                                               const float* __restrict__ alog, const float* __restrict__ Ds, int b0){
    __shared__ __align__(16) float sproj[SEGLEN][12];
    __shared__ float sxc [SEGLEN][128];
    __shared__ float ybuf[SEGLEN][128];
    const int s = blockIdx.x, b = b0 + blockIdx.y, pair = blockIdx.z;
    const int d = threadIdx.x;
    for (int j = d; j < SEGLEN*12; j += 128){
        int i = j / 12, c = j - i*12;
        sproj[i][c] = g_proj[(size_t)(b*LL + scan_pos(pair, s, i))*24 + pair*12 + c];
    }
    const int kf = pair*2, kb_ = pair*2 + 1;
    float4 wf = *(const float4*)&dtw[(size_t)(kf*128 + d)*4];
    float4 wb = *(const float4*)&dtw[(size_t)(kb_*128 + d)*4];
    float bf = dtb[kf*128 + d], bbs = dtb[kb_*128 + d];
    float Af = -ex2f(alog[kf*128 + d] * LOG2E);
    float Ab = -ex2f(alog[kb_*128 + d] * LOG2E);
    const int gf = b*4 + kf, gb = b*4 + kb_;
    __syncthreads();

    float hb = g_init[((size_t)gb*NSEG + (NSEG-1-s))*128 + d];
    #pragma unroll 4
    for (int i = SEGLEN-1; i >= 0; i--){
        int bp = b*LL + scan_pos(pair, s, i);
        float xcv = g_xc[(size_t)bp*128 + d];
        sxc[i][d] = xcv;
        float4 f1 = *(const float4*)&sproj[i][4];
        float4 f2 = *(const float4*)&sproj[i][8];
        float xb = fmaf(wb.x, f1.z, bbs);
        xb = fmaf(wb.y, f1.w, xb);
        xb = fmaf(wb.z, f2.x, xb);
        xb = fmaf(wb.w, f2.y, xb);
        float ub = sp_u(xb);
        float dab = ex2f(Ab * ub);
        float dbb = ub * LN2 * f2.z * xcv;
        hb = fmaf(dab, hb, dbb);
        ybuf[i][d] = hb * f2.w;
    }
    float sumDs = Ds[d] + Ds[128+d] + Ds[256+d] + Ds[384+d];
    float hf = g_init[((size_t)gf*NSEG + s)*128 + d];
    #pragma unroll 4
    for (int i = 0; i < SEGLEN; i++){
        int bp = b*LL + scan_pos(pair, s, i);
        float xcv = sxc[i][d];
        float4 f0 = *(const float4*)&sproj[i][0];
        float4 f1 = *(const float4*)&sproj[i][4];
        float xf = fmaf(wf.x, f0.x, bf);
        xf = fmaf(wf.y, f0.y, xf);
        xf = fmaf(wf.z, f0.z, xf);
        xf = fmaf(wf.w, f0.w, xf);
        float uf = sp_u(xf);
        float daf = ex2f(Af * uf);
        float dbf = uf * LN2 * f1.x * xcv;
        hf = fmaf(daf, hf, dbf);
        float val = fmaf(hf, f1.y, ybuf[i][d]);
        if (pair == 0){
            g_ysum[(size_t)bp*128 + d] = __float2bfloat16(fmaf(xcv, sumDs, val));
        } else {
            g_ysum2[(size_t)bp*128 + d] = __float2bfloat16(val);
        }
    }
}

// ---------------- K6: LayerNorm + SiLU gate + spatial mean (bf16 y input) ----------------
__global__ void __launch_bounds__(256) k_final(const float* __restrict__ nw, const float* __restrict__ nb,
                                               float* __restrict__ out, int b0){
    const int b = b0 + blockIdx.y;
    const int t = threadIdx.x;
    const int warp = t >> 5, lane = t & 31;
    const int d4 = lane*4;
    float4 w4 = *(const float4*)&nw[d4];
    float4 b4 = *(const float4*)&nb[d4];

    float4 acc = make_float4(0.f,0.f,0.f,0.f);
    #pragma unroll 2
    for (int j = 0; j < 8; j++){
        int p = blockIdx.x*64 + warp*8 + j;
        size_t base = ((size_t)(b*LL + p))*128 + d4;
        uint2 u1 = *(const uint2*)&g_ysum[base];
        uint2 u2 = *(const uint2*)&g_ysum2[base];
        float2 a01 = __bfloat1622float2(*reinterpret_cast<__nv_bfloat162*>(&u1.x));
        float2 a23 = __bfloat1622float2(*reinterpret_cast<__nv_bfloat162*>(&u1.y));
        float2 c01 = __bfloat1622float2(*reinterpret_cast<__nv_bfloat162*>(&u2.x));
        float2 c23 = __bfloat1622float2(*reinterpret_cast<__nv_bfloat162*>(&u2.y));
        float4 v;
        v.x = a01.x + c01.x;
        v.y = a01.y + c01.y;
        v.z = a23.x + c23.x;
        v.w = a23.y + c23.y;
        float sm = v.x+v.y+v.z+v.w;
        #pragma unroll
        for (int o = 16; o > 0; o >>= 1) sm += __shfl_xor_sync(~0u, sm, o);
        float mu = sm * (1.f/128.f);
        float4 dv = make_float4(v.x-mu, v.y-mu, v.z-mu, v.w-mu);
        float s2 = dv.x*dv.x + dv.y*dv.y + dv.z*dv.z + dv.w*dv.w;
        #pragma unroll
        for (int o = 16; o > 0; o >>= 1) s2 += __shfl_xor_sync(~0u, s2, o);
        float rstd = rsqrtf(s2 * (1.f/128.f) + 1e-5f);
        float4 z = *(const float4*)&g_xz[((size_t)(b*LL + p))*256 + 128 + d4];
        float gx = z.x*fsigmoid(z.x), gy = z.y*fsigmoid(z.y);
        float gz = z.z*fsigmoid(z.z), gw = z.w*fsigmoid(z.w);
        acc.x = fmaf(fmaf(dv.x*rstd, w4.x, b4.x), gx, acc.x);
        acc.y = fmaf(fmaf(dv.y*rstd, w4.y, b4.y), gy, acc.y);
        acc.z = fmaf(fmaf(dv.z*rstd, w4.z, b4.z), gz, acc.z);
        acc.w = fmaf(fmaf(dv.w*rstd, w4.w, b4.w), gw, acc.w);
    }
    const float sc = 1.f/(float)LL;
    atomicAdd(&out[b*128 + d4 + 0], acc.x*sc);
    atomicAdd(&out[b*128 + d4 + 1], acc.y*sc);
    atomicAdd(&out[b*128 + d4 + 2], acc.z*sc);
    atomicAdd(&out[b*128 + d4 + 3], acc.w*sc);
}

// ---------------- launch: two batch-half chains on forked streams ----------------
extern "C" void kernel_launch(void* const* d_in, const int* in_sizes, int n_in,
                              void* d_out, int out_size){
    const float* x    = (const float*)d_in[0];
    const float* inw  = (const float*)d_in[1];
    const float* cw   = (const float*)d_in[2];
    const float* cb   = (const float*)d_in[3];
    const float* xpw  = (const float*)d_in[4];
    const float* dtw  = (const float*)d_in[5];
    const float* dtb  = (const float*)d_in[6];
    const float* alog = (const float*)d_in[7];
    const float* Ds   = (const float*)d_in[8];
    const float* onw  = (const float*)d_in[9];
    const float* onb  = (const float*)d_in[10];
    float* out = (float*)d_out;

    static cudaStream_t sA = nullptr, sB = nullptr;
    static cudaEvent_t  e0 = nullptr, eA = nullptr, eB = nullptr;
    if (!sA){
        cudaStreamCreateWithFlags(&sA, cudaStreamNonBlocking);
        cudaStreamCreateWithFlags(&sB, cudaStreamNonBlocking);
        cudaEventCreateWithFlags(&e0, cudaEventDisableTiming);
        cudaEventCreateWithFlags(&eA, cudaEventDisableTiming);
        cudaEventCreateWithFlags(&eB, cudaEventDisableTiming);
    }

    k_zero<<<(BB*DD + 255)/256, 256>>>(out);
    cudaEventRecord(e0, 0);
    cudaStreamWaitEvent(sA, e0, 0);
    cudaStreamWaitEvent(sB, e0, 0);

    cudaStream_t ss[2] = { sA, sB };
    #pragma unroll
    for (int hhalf = 0; hhalf < 2; hhalf++){
        cudaStream_t st = ss[hhalf];
        const int b0 = hhalf * HB;
        k_gemm <<<dim3((HB*LL)/128, 4), 256, 0, st>>>(x, inw, b0*LL);
        k_convp<<<(HB*HH*4)/8, 256, 0, st>>>(cw, cb, xpw, b0);
        k_pass1<<<dim3(NSEG, HB, 2), 128, 0, st>>>(dtw, dtb, alog, b0);
        k_comb <<<HB*4, 128, 0, st>>>(b0);
        k_pass2<<<dim3(NSEG, HB, 2), 128, 0, st>>>(dtw, dtb, alog, Ds, b0);
        k_final<<<dim3(LL/64, HB), 256, 0, st>>>(onw, onb, out, b0);
    }
    cudaEventRecord(eA, sA);
    cudaEventRecord(eB, sB);
    cudaStreamWaitEvent(0, eA, 0);
    cudaStreamWaitEvent(0, eB, 0);
}